// round 1
// baseline (speedup 1.0000x reference)
#include <cuda_runtime.h>

// GCN_52046413693566: 3-layer GCN on GB300
// layer: out = (adj .* S) @ (x @ W), relu on layers 1,2.
// B=4, N=4096, F=256, H1=512, H2=1024, C=256.

#define NN 4096
#define BB 4
#define NFEAT 256
#define NHID 512
#define NCLASS 256

// Scratch (static device globals; no runtime allocation allowed)
__device__ float g_Aw[(size_t)NN * NN];                    // adj .* S   (67 MB)
__device__ float g_support[(size_t)BB * NN * (2 * NHID)];  // x @ W      (67 MB)
__device__ float g_h[(size_t)BB * NN * (2 * NHID)];        // layer act  (67 MB)

// ---------------------------------------------------------------------------
// Elementwise: Aw = adj * S  (vectorized float4, grid-stride)
// ---------------------------------------------------------------------------
__global__ void ewmul_kernel(const float* __restrict__ a,
                             const float* __restrict__ s,
                             float* __restrict__ o, int n4) {
    int i = blockIdx.x * blockDim.x + threadIdx.x;
    int stride = gridDim.x * blockDim.x;
    for (; i < n4; i += stride) {
        float4 av = ((const float4*)a)[i];
        float4 sv = ((const float4*)s)[i];
        av.x *= sv.x; av.y *= sv.y; av.z *= sv.z; av.w *= sv.w;
        ((float4*)o)[i] = av;
    }
}

// ---------------------------------------------------------------------------
// Tiled SGEMM: C[M,Ncols] = A[M,K] @ B[K,Ncols], row-major, optional ReLU.
// Blocking: 128x128 tile, BK=8, 256 threads, 8x8 per-thread register tile.
// Batched via blockIdx.z with explicit strides (0 stride = shared operand).
// Requires: M%128==0, Ncols%128==0, K%8==0 (all shapes here satisfy this).
// ---------------------------------------------------------------------------
template <bool RELU>
__global__ __launch_bounds__(256, 2) void sgemm128(
    int M, int Ncols, int K,
    const float* __restrict__ A, const float* __restrict__ Bm,
    float* __restrict__ C,
    long strideA, long strideB, long strideC) {
    constexpr int BM = 128, BN = 128, BK = 8, TM = 8, TN = 8;
    __shared__ float As[BK][BM];
    __shared__ float Bs[BK][BN];

    A  += (long)blockIdx.z * strideA;
    Bm += (long)blockIdx.z * strideB;
    C  += (long)blockIdx.z * strideC;

    const int cRow = blockIdx.y;   // tile row in M
    const int cCol = blockIdx.x;   // tile col in Ncols
    const int tid  = threadIdx.x;

    // per-thread output tile origin
    const int tRow = (tid / (BN / TN)) * TM;   // 16 thread-cols
    const int tCol = (tid % (BN / TN)) * TN;

    // A-tile load mapping: 128 rows x 8 cols = 256 float4 (2 per row)
    const int aRow = tid >> 1;
    const int aCol = (tid & 1) * 4;
    // B-tile load mapping: 8 rows x 128 cols = 256 float4 (32 per row)
    const int bRow = tid >> 5;
    const int bCol = (tid & 31) * 4;

    const float* Aptr = A + (long)(cRow * BM + aRow) * K + aCol;
    const float* Bptr = Bm + (long)bRow * Ncols + (long)cCol * BN + bCol;

    float acc[TM][TN] = {};
    float regA[TM], regB[TN];

    for (int k0 = 0; k0 < K; k0 += BK) {
        float4 av = *(const float4*)Aptr;
        As[aCol + 0][aRow] = av.x;
        As[aCol + 1][aRow] = av.y;
        As[aCol + 2][aRow] = av.z;
        As[aCol + 3][aRow] = av.w;
        float4 bv = *(const float4*)Bptr;
        *(float4*)&Bs[bRow][bCol] = bv;
        __syncthreads();

        Aptr += BK;
        Bptr += (long)BK * Ncols;

#pragma unroll
        for (int k = 0; k < BK; k++) {
#pragma unroll
            for (int i = 0; i < TM; i++) regA[i] = As[k][tRow + i];
#pragma unroll
            for (int j = 0; j < TN; j++) regB[j] = Bs[k][tCol + j];
#pragma unroll
            for (int i = 0; i < TM; i++)
#pragma unroll
                for (int j = 0; j < TN; j++)
                    acc[i][j] = fmaf(regA[i], regB[j], acc[i][j]);
        }
        __syncthreads();
    }

#pragma unroll
    for (int i = 0; i < TM; i++) {
        float* crow = C + (long)(cRow * BM + tRow + i) * Ncols +
                      (long)cCol * BN + tCol;
#pragma unroll
        for (int j = 0; j < TN; j += 4) {
            float4 v = make_float4(acc[i][j], acc[i][j + 1],
                                   acc[i][j + 2], acc[i][j + 3]);
            if (RELU) {
                v.x = fmaxf(v.x, 0.f); v.y = fmaxf(v.y, 0.f);
                v.z = fmaxf(v.z, 0.f); v.w = fmaxf(v.w, 0.f);
            }
            *(float4*)(crow + j) = v;
        }
    }
}

// ---------------------------------------------------------------------------
// Launch: layer-by-layer
// ---------------------------------------------------------------------------
static inline void launch_gemm(bool relu, int M, int Ncols, int K,
                               const float* A, const float* Bm, float* C,
                               long sA, long sB, long sC, int nbatch) {
    dim3 grid(Ncols / 128, M / 128, nbatch);
    if (relu)
        sgemm128<true><<<grid, 256>>>(M, Ncols, K, A, Bm, C, sA, sB, sC);
    else
        sgemm128<false><<<grid, 256>>>(M, Ncols, K, A, Bm, C, sA, sB, sC);
}

extern "C" void kernel_launch(void* const* d_in, const int* in_sizes, int n_in,
                              void* d_out, int out_size) {
    const float* x   = (const float*)d_in[0];  // [B, N, NFEAT]
    const float* adj = (const float*)d_in[1];  // [N, N]
    const float* S   = (const float*)d_in[2];  // [N, N]
    const float* W1  = (const float*)d_in[3];  // [NFEAT, NHID]
    const float* W2  = (const float*)d_in[4];  // [NHID, 2*NHID]
    const float* W3  = (const float*)d_in[5];  // [2*NHID, NCLASS]
    float* out = (float*)d_out;                // [B, N, NCLASS]

    float* Aw = nullptr; float* sup = nullptr; float* h = nullptr;
    cudaGetSymbolAddress((void**)&Aw, g_Aw);
    cudaGetSymbolAddress((void**)&sup, g_support);
    cudaGetSymbolAddress((void**)&h, g_h);

    // 1) Aw = adj .* S
    {
        int n4 = (NN * NN) / 4;
        ewmul_kernel<<<2048, 256>>>(adj, S, Aw, n4);
    }

    const long NS1 = (long)NN * NHID;        // per-batch support stride, layer 1
    const long NS2 = (long)NN * (2 * NHID);  // layer 2
    const long NS3 = (long)NN * NCLASS;      // layer 3

    // Layer 1: support = x @ W1   [B*N, 256] x [256, 512]
    launch_gemm(false, BB * NN, NHID, NFEAT, x, W1, sup, 0, 0, 0, 1);
    // h1 = relu(Aw @ support)  batched over B: [4096,4096] x [4096,512]
    launch_gemm(true, NN, NHID, NN, Aw, sup, h, 0, NS1, NS1, BB);

    // Layer 2: support = h1 @ W2  [B*N, 512] x [512, 1024]
    launch_gemm(false, BB * NN, 2 * NHID, NHID, h, W2, sup, 0, 0, 0, 1);
    // h2 = relu(Aw @ support)  [4096,4096] x [4096,1024]
    launch_gemm(true, NN, 2 * NHID, NN, Aw, sup, h, 0, NS2, NS2, BB);

    // Layer 3: support = h2 @ W3  [B*N, 1024] x [1024, 256]
    launch_gemm(false, BB * NN, NCLASS, 2 * NHID, h, W3, sup, 0, 0, 0, 1);
    // out = Aw @ support  [4096,4096] x [4096,256]  (no relu)
    launch_gemm(false, NN, NCLASS, NN, Aw, sup, out, 0, NS3, NS3, BB);
}

// round 3
// speedup vs baseline: 3.5807x; 3.5807x over previous
#include <cuda_runtime.h>
#include <cuda_bf16.h>
#include <cstdint>

// GCN_52046413693566 — 3-layer GCN via bf16-split mma.sync (legacy tensor pipe).
// D = Ah@Bh + Al@Bh + Ah@Bl  (a = a_hi + a_lo, each bf16) ~ fp32x fp32 to 2^-16.
// B=4, N=4096, F=256, H1=512, H2=1024, C=256.

#define NN 4096
#define BB 4

// ---------------------------------------------------------------------------
// Device scratch. bf16 operands stored PRE-ARRANGED in mma fragment layout:
// A blocks (128m x 16k): [mt(8)][lane(32)][16B = regs a0..a3]
//   block id = mb*(K/16) + kc, 256 uint4 per block.
// B blocks (16k x 128n): [ntpair(8)][lane(32)][16B = b0,b1 of 2 n-tiles]
//   block id = kc*(Ncols/128) + nb, 256 uint4 per block.
// ---------------------------------------------------------------------------
__device__ uint4 g_AwH[(size_t)NN * NN / 8];
__device__ uint4 g_AwL[(size_t)NN * NN / 8];
__device__ uint4 g_AsH[(size_t)BB * NN * 1024 / 8];
__device__ uint4 g_AsL[(size_t)BB * NN * 1024 / 8];
__device__ uint4 g_WH[65536];
__device__ uint4 g_WL[65536];
__device__ uint4 g_BsH[(size_t)BB * NN * 1024 / 8];
__device__ uint4 g_BsL[(size_t)BB * NN * 1024 / 8];
__device__ float g_sup[(size_t)BB * NN * 1024];
__device__ float g_hbuf[(size_t)BB * NN * 1024];

// ---------------------------------------------------------------------------
__device__ __forceinline__ uint32_t smem_u32(const void* p) {
    uint32_t a;
    asm("{ .reg .u64 t; cvta.to.shared.u64 t, %1; cvt.u32.u64 %0, t; }"
        : "=r"(a) : "l"(p));
    return a;
}

__device__ __forceinline__ uint32_t pk(float a, float b) {
    __nv_bfloat162 t = __floats2bfloat162_rn(a, b);
    return *reinterpret_cast<uint32_t*>(&t);
}

__device__ __forceinline__ void split2(float v, float& h, float& l) {
    h = __bfloat162float(__float2bfloat16(v));
    l = v - h;
}

__device__ __forceinline__ void cpa16(uint32_t saddr, const void* gaddr) {
    asm volatile("cp.async.cg.shared.global [%0], [%1], 16;"
                 :: "r"(saddr), "l"(gaddr));
}
#define CP_COMMIT() asm volatile("cp.async.commit_group;" ::: "memory")
#define CP_WAIT2()  asm volatile("cp.async.wait_group 2;" ::: "memory")

__device__ __forceinline__ void mma16816(float* c, const uint4& a,
                                         uint32_t b0, uint32_t b1) {
    asm volatile(
        "mma.sync.aligned.m16n8k16.row.col.f32.bf16.bf16.f32 "
        "{%0,%1,%2,%3},{%4,%5,%6,%7},{%8,%9},{%0,%1,%2,%3};"
        : "+f"(c[0]), "+f"(c[1]), "+f"(c[2]), "+f"(c[3])
        : "r"(a.x), "r"(a.y), "r"(a.z), "r"(a.w), "r"(b0), "r"(b1));
}

// ---------------------------------------------------------------------------
// prep_A: src [M,K] f32 (optional elementwise mul) -> fragment-tiled hi/lo.
// Thread idx == output uint4 index (blk*256 + mt*32 + lane).
// ---------------------------------------------------------------------------
__global__ void prep_A(const float* __restrict__ src,
                       const float* __restrict__ mul,
                       uint4* __restrict__ dhi, uint4* __restrict__ dlo,
                       int M, int K) {
    size_t total = ((size_t)M * K) >> 3;
    int nkc = K >> 4;
    for (size_t idx = (size_t)blockIdx.x * blockDim.x + threadIdx.x; idx < total;
         idx += (size_t)gridDim.x * blockDim.x) {
        int lane = (int)(idx & 31);
        int mt = (int)((idx >> 5) & 7);
        size_t blk = idx >> 8;
        int kc = (int)(blk % nkc);
        size_t mb = blk / nkc;
        int r0 = (int)(mb * 128) + mt * 16 + (lane >> 2);
        int c0 = kc * 16 + (lane & 3) * 2;
        const float* p0 = src + (size_t)r0 * K + c0;
        const float* p1 = p0 + (size_t)8 * K;
        float e[8];
        e[0] = p0[0]; e[1] = p0[1]; e[2] = p1[0]; e[3] = p1[1];
        e[4] = p0[8]; e[5] = p0[9]; e[6] = p1[8]; e[7] = p1[9];
        if (mul) {
            const float* q0 = mul + (size_t)r0 * K + c0;
            const float* q1 = q0 + (size_t)8 * K;
            e[0] *= q0[0]; e[1] *= q0[1]; e[2] *= q1[0]; e[3] *= q1[1];
            e[4] *= q0[8]; e[5] *= q0[9]; e[6] *= q1[8]; e[7] *= q1[9];
        }
        float h[8], l[8];
#pragma unroll
        for (int i = 0; i < 8; i++) split2(e[i], h[i], l[i]);
        uint4 H = make_uint4(pk(h[0], h[1]), pk(h[2], h[3]),
                             pk(h[4], h[5]), pk(h[6], h[7]));
        uint4 L = make_uint4(pk(l[0], l[1]), pk(l[2], l[3]),
                             pk(l[4], l[5]), pk(l[6], l[7]));
        dhi[idx] = H;
        dlo[idx] = L;
    }
}

// ---------------------------------------------------------------------------
// prep_B: src [K,Ncols] f32 row-major -> fragment-tiled hi/lo (batched via z).
// ---------------------------------------------------------------------------
__global__ void prep_B(const float* __restrict__ src,
                       uint4* __restrict__ dhi, uint4* __restrict__ dlo,
                       int K, int Ncols, size_t sSrc, size_t sDst) {
    src += (size_t)blockIdx.z * sSrc;
    dhi += (size_t)blockIdx.z * sDst;
    dlo += (size_t)blockIdx.z * sDst;
    size_t total = ((size_t)K * Ncols) >> 3;
    int nnb = Ncols >> 7;
    for (size_t idx = (size_t)blockIdx.x * blockDim.x + threadIdx.x; idx < total;
         idx += (size_t)gridDim.x * blockDim.x) {
        int lane = (int)(idx & 31);
        int j = (int)((idx >> 5) & 7);   // n-tile pair
        size_t blk = idx >> 8;
        int nb = (int)(blk % nnb);
        int kc = (int)(blk / nnb);
        int n0 = nb * 128 + (2 * j) * 8 + (lane >> 2);
        int k0 = kc * 16 + (lane & 3) * 2;
        const float* pk0 = src + (size_t)k0 * Ncols;
        float e[8];
        e[0] = pk0[n0];               e[1] = pk0[Ncols + n0];
        e[2] = pk0[8 * Ncols + n0];   e[3] = pk0[9 * Ncols + n0];
        e[4] = pk0[n0 + 8];           e[5] = pk0[Ncols + n0 + 8];
        e[6] = pk0[8 * Ncols + n0 + 8]; e[7] = pk0[9 * Ncols + n0 + 8];
        float h[8], l[8];
#pragma unroll
        for (int i = 0; i < 8; i++) split2(e[i], h[i], l[i]);
        uint4 H = make_uint4(pk(h[0], h[1]), pk(h[2], h[3]),
                             pk(h[4], h[5]), pk(h[6], h[7]));
        uint4 L = make_uint4(pk(l[0], l[1]), pk(l[2], l[3]),
                             pk(l[4], l[5]), pk(l[6], l[7]));
        dhi[idx] = H;
        dlo[idx] = L;
    }
}

// ---------------------------------------------------------------------------
// GEMM: C[M,Ncols] = A@B (+relu). BM=128, BN=128, BK=16, 4-stage cp.async.
// 256 threads = 8 warps (2m x 4n), warp tile 64x32, mma.m16n8k16 bf16.
// Per k-chunk: 3 products (AhBh, AlBh, AhBl).
// ---------------------------------------------------------------------------
template <bool RELU>
__global__ __launch_bounds__(256)
void gemm_bf16x3(const uint4* __restrict__ Ah, const uint4* __restrict__ Al,
                 const uint4* __restrict__ Bh, const uint4* __restrict__ Bl,
                 float* __restrict__ C, int Ncols, int K,
                 size_t sBu4, size_t sCf) {
    extern __shared__ __align__(128) char sm[];
    const int tid = threadIdx.x;
    const int lane = tid & 31;
    const int wid = tid >> 5;
    const int wm = wid >> 2;    // 0..1
    const int wn = wid & 3;     // 0..3
    const int bx = blockIdx.x, by = blockIdx.y, bz = blockIdx.z;

    Bh += (size_t)bz * sBu4;
    Bl += (size_t)bz * sBu4;
    C  += (size_t)bz * sCf;

    const int nk = K >> 4;
    const int nnb = Ncols >> 7;
    const uint32_t sbase = smem_u32(sm);

    float acc[4][4][4];
#pragma unroll
    for (int i = 0; i < 4; i++)
#pragma unroll
        for (int j = 0; j < 4; j++)
#pragma unroll
            for (int r = 0; r < 4; r++) acc[i][j][r] = 0.f;

    auto issue = [&](int s, int c) {
        size_t ablk = ((size_t)by * nk + c) * 256 + tid;
        size_t bblk = ((size_t)c * nnb + bx) * 256 + tid;
        uint32_t sa = sbase + s * 16384 + tid * 16;
        cpa16(sa,          Ah + ablk);
        cpa16(sa + 4096,   Al + ablk);
        cpa16(sa + 8192,   Bh + bblk);
        cpa16(sa + 12288,  Bl + bblk);
    };

    issue(0, 0); CP_COMMIT();
    issue(1, 1); CP_COMMIT();
    issue(2, 2); CP_COMMIT();

    for (int c = 0; c < nk; ++c) {
        int s = c & 3;
        CP_WAIT2();
        __syncthreads();

        const uint4* sAh = (const uint4*)(sm + s * 16384);
        const uint4* sAl = sAh + 256;
        const uint4* sBh = sAh + 512;
        const uint4* sBl = sAh + 768;

        uint4 fAh[4], fAl[4], fBh[2], fBl[2];
#pragma unroll
        for (int i = 0; i < 4; i++) {
            fAh[i] = sAh[(wm * 4 + i) * 32 + lane];
            fAl[i] = sAl[(wm * 4 + i) * 32 + lane];
        }
#pragma unroll
        for (int q = 0; q < 2; q++) {
            fBh[q] = sBh[(wn * 2 + q) * 32 + lane];
            fBl[q] = sBl[(wn * 2 + q) * 32 + lane];
        }

#pragma unroll
        for (int i = 0; i < 4; i++) {
#pragma unroll
            for (int j = 0; j < 4; j++) {
                int q = j >> 1;
                uint32_t bh0 = (j & 1) ? fBh[q].z : fBh[q].x;
                uint32_t bh1 = (j & 1) ? fBh[q].w : fBh[q].y;
                uint32_t bl0 = (j & 1) ? fBl[q].z : fBl[q].x;
                uint32_t bl1 = (j & 1) ? fBl[q].w : fBl[q].y;
                mma16816(acc[i][j], fAh[i], bh0, bh1);
                mma16816(acc[i][j], fAl[i], bh0, bh1);
                mma16816(acc[i][j], fAh[i], bl0, bl1);
            }
        }
        __syncthreads();
        if (c + 3 < nk) issue((c + 3) & 3, c + 3);
        CP_COMMIT();   // commit every iteration (possibly empty) to keep
                       // wait_group<2> aligned with chunk completion
    }

    // Epilogue
    const int row0 = by * 128 + wm * 64 + (lane >> 2);
    const int colb = bx * 128 + wn * 32 + (lane & 3) * 2;
#pragma unroll
    for (int i = 0; i < 4; i++) {
#pragma unroll
        for (int j = 0; j < 4; j++) {
            int r = row0 + i * 16;
            int col = colb + j * 8;
            float2 v01 = make_float2(acc[i][j][0], acc[i][j][1]);
            float2 v23 = make_float2(acc[i][j][2], acc[i][j][3]);
            if (RELU) {
                v01.x = fmaxf(v01.x, 0.f); v01.y = fmaxf(v01.y, 0.f);
                v23.x = fmaxf(v23.x, 0.f); v23.y = fmaxf(v23.y, 0.f);
            }
            *reinterpret_cast<float2*>(C + (size_t)r * Ncols + col) = v01;
            *reinterpret_cast<float2*>(C + (size_t)(r + 8) * Ncols + col) = v23;
        }
    }
}

// ---------------------------------------------------------------------------
// Host
// ---------------------------------------------------------------------------
static void launch_gemm(bool relu, int M, int Ncols, int K,
                        const uint4* Ah, const uint4* Al,
                        const uint4* Bh, const uint4* Bl, float* C,
                        int batch, size_t sBu4, size_t sCf) {
    dim3 g(Ncols / 128, M / 128, batch);
    int smem = 4 * 16384;
    if (relu) {
        cudaFuncSetAttribute(gemm_bf16x3<true>,
                             cudaFuncAttributeMaxDynamicSharedMemorySize, smem);
        gemm_bf16x3<true><<<g, 256, smem>>>(Ah, Al, Bh, Bl, C, Ncols, K, sBu4, sCf);
    } else {
        cudaFuncSetAttribute(gemm_bf16x3<false>,
                             cudaFuncAttributeMaxDynamicSharedMemorySize, smem);
        gemm_bf16x3<false><<<g, 256, smem>>>(Ah, Al, Bh, Bl, C, Ncols, K, sBu4, sCf);
    }
}

extern "C" void kernel_launch(void* const* d_in, const int* in_sizes, int n_in,
                              void* d_out, int out_size) {
    const float* x   = (const float*)d_in[0];  // [B, N, 256]
    const float* adj = (const float*)d_in[1];  // [N, N]
    const float* S   = (const float*)d_in[2];  // [N, N]
    const float* W1  = (const float*)d_in[3];  // [256, 512]
    const float* W2  = (const float*)d_in[4];  // [512, 1024]
    const float* W3  = (const float*)d_in[5];  // [1024, 256]
    float* out = (float*)d_out;                // [B, N, 256]

    uint4 *AwH, *AwL, *AsH, *AsL, *WH, *WL, *BsH, *BsL;
    float *sup, *hbuf;
    cudaGetSymbolAddress((void**)&AwH, g_AwH);
    cudaGetSymbolAddress((void**)&AwL, g_AwL);
    cudaGetSymbolAddress((void**)&AsH, g_AsH);
    cudaGetSymbolAddress((void**)&AsL, g_AsL);
    cudaGetSymbolAddress((void**)&WH, g_WH);
    cudaGetSymbolAddress((void**)&WL, g_WL);
    cudaGetSymbolAddress((void**)&BsH, g_BsH);
    cudaGetSymbolAddress((void**)&BsL, g_BsL);
    cudaGetSymbolAddress((void**)&sup, g_sup);
    cudaGetSymbolAddress((void**)&hbuf, g_hbuf);

    // Aw = adj .* S  (fragment-tiled hi/lo; A operand of all big GEMMs)
    prep_A<<<2048, 256>>>(adj, S, AwH, AwL, NN, NN);

    // ---- Layer 1 ----
    prep_A<<<1024, 256>>>(x, nullptr, AsH, AsL, BB * NN, 256);
    prep_B<<<64, 256>>>(W1, WH, WL, 256, 512, 0, 0);
    launch_gemm(false, BB * NN, 512, 256, AsH, AsL, WH, WL, sup, 1, 0, 0);
    prep_B<<<dim3(512, 1, BB), 256>>>(sup, BsH, BsL, NN, 512,
                                      (size_t)NN * 512, (size_t)NN * 512 / 8);
    launch_gemm(true, NN, 512, NN, AwH, AwL, BsH, BsL, hbuf, BB,
                (size_t)NN * 512 / 8, (size_t)NN * 512);

    // ---- Layer 2 ----
    prep_A<<<2048, 256>>>(hbuf, nullptr, AsH, AsL, BB * NN, 512);
    prep_B<<<256, 256>>>(W2, WH, WL, 512, 1024, 0, 0);
    launch_gemm(false, BB * NN, 1024, 512, AsH, AsL, WH, WL, sup, 1, 0, 0);
    prep_B<<<dim3(1024, 1, BB), 256>>>(sup, BsH, BsL, NN, 1024,
                                       (size_t)NN * 1024, (size_t)NN * 1024 / 8);
    launch_gemm(true, NN, 1024, NN, AwH, AwL, BsH, BsL, hbuf, BB,
                (size_t)NN * 1024 / 8, (size_t)NN * 1024);

    // ---- Layer 3 ----
    prep_A<<<2048, 256>>>(hbuf, nullptr, AsH, AsL, BB * NN, 1024);
    prep_B<<<128, 256>>>(W3, WH, WL, 1024, 256, 0, 0);
    launch_gemm(false, BB * NN, 256, 1024, AsH, AsL, WH, WL, sup, 1, 0, 0);
    prep_B<<<dim3(512, 1, BB), 256>>>(sup, BsH, BsL, NN, 256,
                                      (size_t)NN * 256, (size_t)NN * 256 / 8);
    launch_gemm(false, NN, 256, NN, AwH, AwL, BsH, BsL, out, BB,
                (size_t)NN * 256 / 8, (size_t)NN * 256);
}

// round 4
// speedup vs baseline: 3.6801x; 1.0278x over previous
#include <cuda_runtime.h>
#include <cuda_bf16.h>
#include <cstdint>

// GCN — 3-layer GCN via bf16-split mma.sync. D = AhBh + AlBh + AhBl.
// R4: BK=32/1-sync mainloop, 2-CTA occupancy, batch-major grid for Aw L2
// reuse, big-GEMM epilogue emits next-layer A fragments (relu fused).

#define NN 4096
#define BB 4

// Fragment-tiled storage (see R3 comment): A blocks 128x16 = 256 uint4,
// B blocks 16x128 = 256 uint4.
__device__ uint4 g_AwH[(size_t)NN * NN / 8];
__device__ uint4 g_AwL[(size_t)NN * NN / 8];
__device__ uint4 g_AsH[(size_t)BB * NN * 1024 / 8];
__device__ uint4 g_AsL[(size_t)BB * NN * 1024 / 8];
__device__ uint4 g_WH[65536];
__device__ uint4 g_WL[65536];
__device__ uint4 g_BsH[(size_t)BB * NN * 1024 / 8];
__device__ uint4 g_BsL[(size_t)BB * NN * 1024 / 8];
__device__ float g_sup[(size_t)BB * NN * 1024];

// ---------------------------------------------------------------------------
__device__ __forceinline__ uint32_t smem_u32(const void* p) {
    uint32_t a;
    asm("{ .reg .u64 t; cvta.to.shared.u64 t, %1; cvt.u32.u64 %0, t; }"
        : "=r"(a) : "l"(p));
    return a;
}
__device__ __forceinline__ uint32_t pk(float a, float b) {
    __nv_bfloat162 t = __floats2bfloat162_rn(a, b);
    return *reinterpret_cast<uint32_t*>(&t);
}
__device__ __forceinline__ void split2(float v, float& h, float& l) {
    h = __bfloat162float(__float2bfloat16(v));
    l = v - h;
}
__device__ __forceinline__ void cpa16(uint32_t saddr, const void* gaddr) {
    asm volatile("cp.async.cg.shared.global [%0], [%1], 16;"
                 :: "r"(saddr), "l"(gaddr));
}
#define CP_COMMIT() asm volatile("cp.async.commit_group;" ::: "memory")
#define CP_WAIT1()  asm volatile("cp.async.wait_group 1;" ::: "memory")

__device__ __forceinline__ void mma16816(float* c, const uint4& a,
                                         uint32_t b0, uint32_t b1) {
    asm volatile(
        "mma.sync.aligned.m16n8k16.row.col.f32.bf16.bf16.f32 "
        "{%0,%1,%2,%3},{%4,%5,%6,%7},{%8,%9},{%0,%1,%2,%3};"
        : "+f"(c[0]), "+f"(c[1]), "+f"(c[2]), "+f"(c[3])
        : "r"(a.x), "r"(a.y), "r"(a.z), "r"(a.w), "r"(b0), "r"(b1));
}

// ---------------------------------------------------------------------------
// prep_A: src [M,K] f32 (optional elementwise mul) -> fragment-tiled hi/lo
// ---------------------------------------------------------------------------
__global__ void prep_A(const float* __restrict__ src,
                       const float* __restrict__ mul,
                       uint4* __restrict__ dhi, uint4* __restrict__ dlo,
                       int M, int K) {
    size_t total = ((size_t)M * K) >> 3;
    int nkc = K >> 4;
    for (size_t idx = (size_t)blockIdx.x * blockDim.x + threadIdx.x; idx < total;
         idx += (size_t)gridDim.x * blockDim.x) {
        int lane = (int)(idx & 31);
        int mt = (int)((idx >> 5) & 7);
        size_t blk = idx >> 8;
        int kc = (int)(blk % nkc);
        size_t mb = blk / nkc;
        int r0 = (int)(mb * 128) + mt * 16 + (lane >> 2);
        int c0 = kc * 16 + (lane & 3) * 2;
        const float* p0 = src + (size_t)r0 * K + c0;
        const float* p1 = p0 + (size_t)8 * K;
        float e[8];
        e[0] = p0[0]; e[1] = p0[1]; e[2] = p1[0]; e[3] = p1[1];
        e[4] = p0[8]; e[5] = p0[9]; e[6] = p1[8]; e[7] = p1[9];
        if (mul) {
            const float* q0 = mul + (size_t)r0 * K + c0;
            const float* q1 = q0 + (size_t)8 * K;
            e[0] *= q0[0]; e[1] *= q0[1]; e[2] *= q1[0]; e[3] *= q1[1];
            e[4] *= q0[8]; e[5] *= q0[9]; e[6] *= q1[8]; e[7] *= q1[9];
        }
        float h[8], l[8];
#pragma unroll
        for (int i = 0; i < 8; i++) split2(e[i], h[i], l[i]);
        dhi[idx] = make_uint4(pk(h[0], h[1]), pk(h[2], h[3]),
                              pk(h[4], h[5]), pk(h[6], h[7]));
        dlo[idx] = make_uint4(pk(l[0], l[1]), pk(l[2], l[3]),
                              pk(l[4], l[5]), pk(l[6], l[7]));
    }
}

// ---------------------------------------------------------------------------
// prep_B: src [K,Ncols] f32 row-major -> fragment-tiled hi/lo (batch via z)
// ---------------------------------------------------------------------------
__global__ void prep_B(const float* __restrict__ src,
                       uint4* __restrict__ dhi, uint4* __restrict__ dlo,
                       int K, int Ncols, size_t sSrc, size_t sDst) {
    src += (size_t)blockIdx.z * sSrc;
    dhi += (size_t)blockIdx.z * sDst;
    dlo += (size_t)blockIdx.z * sDst;
    size_t total = ((size_t)K * Ncols) >> 3;
    int nnb = Ncols >> 7;
    for (size_t idx = (size_t)blockIdx.x * blockDim.x + threadIdx.x; idx < total;
         idx += (size_t)gridDim.x * blockDim.x) {
        int lane = (int)(idx & 31);
        int j = (int)((idx >> 5) & 7);
        size_t blk = idx >> 8;
        int nb = (int)(blk % nnb);
        int kc = (int)(blk / nnb);
        int n0 = nb * 128 + (2 * j) * 8 + (lane >> 2);
        int k0 = kc * 16 + (lane & 3) * 2;
        const float* pk0 = src + (size_t)k0 * Ncols;
        float e[8];
        e[0] = pk0[n0];                 e[1] = pk0[Ncols + n0];
        e[2] = pk0[8 * Ncols + n0];     e[3] = pk0[9 * Ncols + n0];
        e[4] = pk0[n0 + 8];             e[5] = pk0[Ncols + n0 + 8];
        e[6] = pk0[8 * Ncols + n0 + 8]; e[7] = pk0[9 * Ncols + n0 + 8];
        float h[8], l[8];
#pragma unroll
        for (int i = 0; i < 8; i++) split2(e[i], h[i], l[i]);
        dhi[idx] = make_uint4(pk(h[0], h[1]), pk(h[2], h[3]),
                              pk(h[4], h[5]), pk(h[6], h[7]));
        dlo[idx] = make_uint4(pk(l[0], l[1]), pk(l[2], l[3]),
                              pk(l[4], l[5]), pk(l[6], l[7]));
    }
}

// ---------------------------------------------------------------------------
// GEMM: BM=128, BN=128, BK=32, 3-stage cp.async (32KB/stage), 8 warps 2x4,
// warp tile 64x32, 3 products per mma site.
// MODE 0: fp32 out, no relu.  MODE 1: relu + emit next-layer A frags (hi/lo).
// grid: x = nbX*batch (bx = x%nbX, bz = x/nbX), y = M/128.
// ---------------------------------------------------------------------------
template <int MODE>
__global__ __launch_bounds__(256, 2)
void gemm_bf16x3(const uint4* __restrict__ Ah, const uint4* __restrict__ Al,
                 const uint4* __restrict__ Bh, const uint4* __restrict__ Bl,
                 float* __restrict__ C, uint4* __restrict__ FH,
                 uint4* __restrict__ FL, int Ncols, int K, int nbX,
                 size_t sBu4, size_t sCf, int mbPerBatch) {
    extern __shared__ __align__(128) char sm[];
    const int tid = threadIdx.x;
    const int lane = tid & 31;
    const int wid = tid >> 5;
    const int wm = wid >> 2;
    const int wn = wid & 3;
    const int bx = blockIdx.x % nbX;
    const int bz = blockIdx.x / nbX;
    const int by = blockIdx.y;

    Bh += (size_t)bz * sBu4;
    Bl += (size_t)bz * sBu4;

    const int nc2 = K >> 5;        // 32-k chunks
    const int nkc = K >> 4;        // 16-k frag blocks
    const int nnb = Ncols >> 7;
    const uint32_t sbase = smem_u32(sm);

    float acc[4][4][4];
#pragma unroll
    for (int i = 0; i < 4; i++)
#pragma unroll
        for (int j = 0; j < 4; j++)
#pragma unroll
            for (int r = 0; r < 4; r++) acc[i][j][r] = 0.f;

    auto issue = [&](int s, int c) {
        uint32_t sa = sbase + s * 32768 + tid * 16;
        size_t ab = ((size_t)by * nkc + (size_t)(c << 1)) * 256 + tid;
        size_t bb0 = ((size_t)(c << 1) * nnb + bx) * 256 + tid;
        size_t bb1 = bb0 + (size_t)nnb * 256;
        cpa16(sa,          Ah + ab);
        cpa16(sa + 4096,   Ah + ab + 256);
        cpa16(sa + 8192,   Al + ab);
        cpa16(sa + 12288,  Al + ab + 256);
        cpa16(sa + 16384,  Bh + bb0);
        cpa16(sa + 20480,  Bh + bb1);
        cpa16(sa + 24576,  Bl + bb0);
        cpa16(sa + 28672,  Bl + bb1);
    };

    issue(0, 0); CP_COMMIT();
    issue(1, 1); CP_COMMIT();

    for (int c = 0; c < nc2; ++c) {
        int s = c % 3;
        CP_WAIT1();
        __syncthreads();
        const char* st = sm + s * 32768;
#pragma unroll
        for (int kk = 0; kk < 2; ++kk) {
            const uint4* sAh = (const uint4*)(st + kk * 4096);
            const uint4* sAl = (const uint4*)(st + 8192 + kk * 4096);
            const uint4* sBh = (const uint4*)(st + 16384 + kk * 4096);
            const uint4* sBl = (const uint4*)(st + 24576 + kk * 4096);
            uint4 fAh[4], fAl[4], fBh[2], fBl[2];
#pragma unroll
            for (int i = 0; i < 4; i++) {
                fAh[i] = sAh[(wm * 4 + i) * 32 + lane];
                fAl[i] = sAl[(wm * 4 + i) * 32 + lane];
            }
#pragma unroll
            for (int q = 0; q < 2; q++) {
                fBh[q] = sBh[(wn * 2 + q) * 32 + lane];
                fBl[q] = sBl[(wn * 2 + q) * 32 + lane];
            }
#pragma unroll
            for (int i = 0; i < 4; i++) {
#pragma unroll
                for (int j = 0; j < 4; j++) {
                    int q = j >> 1;
                    uint32_t bh0 = (j & 1) ? fBh[q].z : fBh[q].x;
                    uint32_t bh1 = (j & 1) ? fBh[q].w : fBh[q].y;
                    uint32_t bl0 = (j & 1) ? fBl[q].z : fBl[q].x;
                    uint32_t bl1 = (j & 1) ? fBl[q].w : fBl[q].y;
                    mma16816(acc[i][j], fAh[i], bh0, bh1);
                    mma16816(acc[i][j], fAl[i], bh0, bh1);
                    mma16816(acc[i][j], fAh[i], bl0, bl1);
                }
            }
        }
        if (c + 2 < nc2) issue((c + 2) % 3, c + 2);
        CP_COMMIT();
    }

    if (MODE == 0) {
        float* Cb = C + (size_t)bz * sCf;
        const int row0 = by * 128 + wm * 64 + (lane >> 2);
        const int colb = bx * 128 + wn * 32 + (lane & 3) * 2;
#pragma unroll
        for (int i = 0; i < 4; i++) {
#pragma unroll
            for (int j = 0; j < 4; j++) {
                int r = row0 + i * 16;
                int col = colb + j * 8;
                *reinterpret_cast<float2*>(Cb + (size_t)r * Ncols + col) =
                    make_float2(acc[i][j][0], acc[i][j][1]);
                *reinterpret_cast<float2*>(Cb + (size_t)(r + 8) * Ncols + col) =
                    make_float2(acc[i][j][2], acc[i][j][3]);
            }
        }
    } else {
        // relu + split + emit A fragments for the next layer.
        // next-layer A: M rows (same), K = Ncols. frag block = mb*nkNext+kcg.
        const int nkNext = Ncols >> 4;
        const size_t mb = (size_t)bz * mbPerBatch + by;
#pragma unroll
        for (int i = 0; i < 4; i++) {
#pragma unroll
            for (int jp = 0; jp < 2; jp++) {
                float v[8];
#pragma unroll
                for (int r = 0; r < 4; r++) {
                    v[r]     = fmaxf(acc[i][2 * jp][r], 0.f);
                    v[4 + r] = fmaxf(acc[i][2 * jp + 1][r], 0.f);
                }
                float h[8], l[8];
#pragma unroll
                for (int r = 0; r < 8; r++) split2(v[r], h[r], l[r]);
                int kcg = bx * 8 + wn * 2 + jp;
                size_t di = (mb * nkNext + kcg) * 256 + (wm * 4 + i) * 32 + lane;
                FH[di] = make_uint4(pk(h[0], h[1]), pk(h[2], h[3]),
                                    pk(h[4], h[5]), pk(h[6], h[7]));
                FL[di] = make_uint4(pk(l[0], l[1]), pk(l[2], l[3]),
                                    pk(l[4], l[5]), pk(l[6], l[7]));
            }
        }
    }
}

// ---------------------------------------------------------------------------
static void launch_gemm(int mode, int M, int Ncols, int K,
                        const uint4* Ah, const uint4* Al,
                        const uint4* Bh, const uint4* Bl,
                        float* C, uint4* FH, uint4* FL,
                        int batch, size_t sBu4, size_t sCf, int mbPerBatch) {
    int nbX = Ncols / 128;
    dim3 g(nbX * batch, M / 128);
    int smem = 3 * 32768;
    if (mode == 1) {
        cudaFuncSetAttribute(gemm_bf16x3<1>,
                             cudaFuncAttributeMaxDynamicSharedMemorySize, smem);
        gemm_bf16x3<1><<<g, 256, smem>>>(Ah, Al, Bh, Bl, C, FH, FL, Ncols, K,
                                         nbX, sBu4, sCf, mbPerBatch);
    } else {
        cudaFuncSetAttribute(gemm_bf16x3<0>,
                             cudaFuncAttributeMaxDynamicSharedMemorySize, smem);
        gemm_bf16x3<0><<<g, 256, smem>>>(Ah, Al, Bh, Bl, C, FH, FL, Ncols, K,
                                         nbX, sBu4, sCf, mbPerBatch);
    }
}

extern "C" void kernel_launch(void* const* d_in, const int* in_sizes, int n_in,
                              void* d_out, int out_size) {
    const float* x   = (const float*)d_in[0];
    const float* adj = (const float*)d_in[1];
    const float* S   = (const float*)d_in[2];
    const float* W1  = (const float*)d_in[3];
    const float* W2  = (const float*)d_in[4];
    const float* W3  = (const float*)d_in[5];
    float* out = (float*)d_out;

    uint4 *AwH, *AwL, *AsH, *AsL, *WH, *WL, *BsH, *BsL;
    float* sup;
    cudaGetSymbolAddress((void**)&AwH, g_AwH);
    cudaGetSymbolAddress((void**)&AwL, g_AwL);
    cudaGetSymbolAddress((void**)&AsH, g_AsH);
    cudaGetSymbolAddress((void**)&AsL, g_AsL);
    cudaGetSymbolAddress((void**)&WH, g_WH);
    cudaGetSymbolAddress((void**)&WL, g_WL);
    cudaGetSymbolAddress((void**)&BsH, g_BsH);
    cudaGetSymbolAddress((void**)&BsL, g_BsL);
    cudaGetSymbolAddress((void**)&sup, g_sup);

    // Aw = adj .* S (A operand of all big GEMMs)
    prep_A<<<2048, 256>>>(adj, S, AwH, AwL, NN, NN);

    // ---- Layer 1 ----
    prep_A<<<1024, 256>>>(x, nullptr, AsH, AsL, BB * NN, 256);
    prep_B<<<64, 256>>>(W1, WH, WL, 256, 512, 0, 0);
    launch_gemm(0, BB * NN, 512, 256, AsH, AsL, WH, WL, sup, nullptr, nullptr,
                1, 0, 0, 0);
    prep_B<<<dim3(512, 1, BB), 256>>>(sup, BsH, BsL, NN, 512,
                                      (size_t)NN * 512, (size_t)NN * 512 / 8);
    // big GEMM: relu + emit layer-2 A frags (K_next = 512)
    launch_gemm(1, NN, 512, NN, AwH, AwL, BsH, BsL, nullptr, AsH, AsL,
                BB, (size_t)NN * 512 / 8, 0, NN / 128);

    // ---- Layer 2 ----
    prep_B<<<256, 256>>>(W2, WH, WL, 512, 1024, 0, 0);
    launch_gemm(0, BB * NN, 1024, 512, AsH, AsL, WH, WL, sup, nullptr, nullptr,
                1, 0, 0, 0);
    prep_B<<<dim3(1024, 1, BB), 256>>>(sup, BsH, BsL, NN, 1024,
                                       (size_t)NN * 1024, (size_t)NN * 1024 / 8);
    launch_gemm(1, NN, 1024, NN, AwH, AwL, BsH, BsL, nullptr, AsH, AsL,
                BB, (size_t)NN * 1024 / 8, 0, NN / 128);

    // ---- Layer 3 ----
    prep_B<<<128, 256>>>(W3, WH, WL, 1024, 256, 0, 0);
    launch_gemm(0, BB * NN, 256, 1024, AsH, AsL, WH, WL, sup, nullptr, nullptr,
                1, 0, 0, 0);
    prep_B<<<dim3(512, 1, BB), 256>>>(sup, BsH, BsL, NN, 256,
                                      (size_t)NN * 256, (size_t)NN * 256 / 8);
    launch_gemm(0, NN, 256, NN, AwH, AwL, BsH, BsL, out, nullptr, nullptr,
                BB, (size_t)NN * 256 / 8, (size_t)NN * 256, 0);
}

// round 5
// speedup vs baseline: 5.5231x; 1.5008x over previous
#include <cuda_runtime.h>
#include <cuda_bf16.h>
#include <cstdint>

// GCN — reassociated 3-layer GCN, bf16-split mma.sync (D = AhBh+AlBh+AhBl).
// t1=Aw@x; h1=relu(t1@W1); t2=Aw@h1; h2=relu(t2@W2); s3=h2@W3; out=Aw@s3.
// All intermediates flow as bf16 hi/lo mma fragments (no fp32 round-trips).

#define NN 4096
#define BB 4

// Fragment-tiled storage: A blocks 128m x 16k = 256 uint4 (block = mb*nkc+kc),
// B blocks 16k x 128n = 256 uint4 (block = kc*nnb+nb).
__device__ uint4 g_AwH[(size_t)NN * NN / 8];
__device__ uint4 g_AwL[(size_t)NN * NN / 8];
__device__ uint4 g_FaH[(size_t)BB * NN * 1024 / 8];  // ping
__device__ uint4 g_FaL[(size_t)BB * NN * 1024 / 8];
__device__ uint4 g_FbH[(size_t)BB * NN * 1024 / 8];  // pong
__device__ uint4 g_FbL[(size_t)BB * NN * 1024 / 8];
__device__ uint4 g_WH[114688];  // W1@0 (16384), W2@16384 (65536), W3@81920 (32768)
__device__ uint4 g_WL[114688];

// ---------------------------------------------------------------------------
__device__ __forceinline__ uint32_t smem_u32(const void* p) {
    uint32_t a;
    asm("{ .reg .u64 t; cvta.to.shared.u64 t, %1; cvt.u32.u64 %0, t; }"
        : "=r"(a) : "l"(p));
    return a;
}
__device__ __forceinline__ uint32_t pk(float a, float b) {
    __nv_bfloat162 t = __floats2bfloat162_rn(a, b);
    return *reinterpret_cast<uint32_t*>(&t);
}
__device__ __forceinline__ void split2(float v, float& h, float& l) {
    h = __bfloat162float(__float2bfloat16(v));
    l = v - h;
}
__device__ __forceinline__ void cpa16(uint32_t saddr, const void* gaddr) {
    asm volatile("cp.async.cg.shared.global [%0], [%1], 16;"
                 :: "r"(saddr), "l"(gaddr));
}
#define CP_COMMIT() asm volatile("cp.async.commit_group;" ::: "memory")
#define CP_WAIT1()  asm volatile("cp.async.wait_group 1;" ::: "memory")
#define CP_WAIT0()  asm volatile("cp.async.wait_group 0;" ::: "memory")

__device__ __forceinline__ void mma16816(float* c, const uint4& a,
                                         uint32_t b0, uint32_t b1) {
    asm volatile(
        "mma.sync.aligned.m16n8k16.row.col.f32.bf16.bf16.f32 "
        "{%0,%1,%2,%3},{%4,%5,%6,%7},{%8,%9},{%0,%1,%2,%3};"
        : "+f"(c[0]), "+f"(c[1]), "+f"(c[2]), "+f"(c[3])
        : "r"(a.x), "r"(a.y), "r"(a.z), "r"(a.w), "r"(b0), "r"(b1));
}

// ---------------------------------------------------------------------------
// prep_A: src [M,K] f32 (optional elementwise mul) -> A-frag hi/lo
// ---------------------------------------------------------------------------
__global__ void prep_A(const float* __restrict__ src,
                       const float* __restrict__ mul,
                       uint4* __restrict__ dhi, uint4* __restrict__ dlo,
                       int M, int K) {
    size_t total = ((size_t)M * K) >> 3;
    int nkc = K >> 4;
    for (size_t idx = (size_t)blockIdx.x * blockDim.x + threadIdx.x; idx < total;
         idx += (size_t)gridDim.x * blockDim.x) {
        int lane = (int)(idx & 31);
        int mt = (int)((idx >> 5) & 7);
        size_t blk = idx >> 8;
        int kc = (int)(blk % nkc);
        size_t mb = blk / nkc;
        int r0 = (int)(mb * 128) + mt * 16 + (lane >> 2);
        int c0 = kc * 16 + (lane & 3) * 2;
        const float* p0 = src + (size_t)r0 * K + c0;
        const float* p1 = p0 + (size_t)8 * K;
        float e[8];
        e[0] = p0[0]; e[1] = p0[1]; e[2] = p1[0]; e[3] = p1[1];
        e[4] = p0[8]; e[5] = p0[9]; e[6] = p1[8]; e[7] = p1[9];
        if (mul) {
            const float* q0 = mul + (size_t)r0 * K + c0;
            const float* q1 = q0 + (size_t)8 * K;
            e[0] *= q0[0]; e[1] *= q0[1]; e[2] *= q1[0]; e[3] *= q1[1];
            e[4] *= q0[8]; e[5] *= q0[9]; e[6] *= q1[8]; e[7] *= q1[9];
        }
        float h[8], l[8];
#pragma unroll
        for (int i = 0; i < 8; i++) split2(e[i], h[i], l[i]);
        dhi[idx] = make_uint4(pk(h[0], h[1]), pk(h[2], h[3]),
                              pk(h[4], h[5]), pk(h[6], h[7]));
        dlo[idx] = make_uint4(pk(l[0], l[1]), pk(l[2], l[3]),
                              pk(l[4], l[5]), pk(l[6], l[7]));
    }
}

// ---------------------------------------------------------------------------
// prep_B: src [K,Ncols] f32 row-major -> B-frag hi/lo (batch via z)
// ---------------------------------------------------------------------------
__global__ void prep_B(const float* __restrict__ src,
                       uint4* __restrict__ dhi, uint4* __restrict__ dlo,
                       int K, int Ncols, size_t sSrc, size_t sDst) {
    src += (size_t)blockIdx.z * sSrc;
    dhi += (size_t)blockIdx.z * sDst;
    dlo += (size_t)blockIdx.z * sDst;
    size_t total = ((size_t)K * Ncols) >> 3;
    int nnb = Ncols >> 7;
    for (size_t idx = (size_t)blockIdx.x * blockDim.x + threadIdx.x; idx < total;
         idx += (size_t)gridDim.x * blockDim.x) {
        int lane = (int)(idx & 31);
        int j = (int)((idx >> 5) & 7);
        size_t blk = idx >> 8;
        int nb = (int)(blk % nnb);
        int kc = (int)(blk / nnb);
        int n0 = nb * 128 + (2 * j) * 8 + (lane >> 2);
        int k0 = kc * 16 + (lane & 3) * 2;
        const float* pk0 = src + (size_t)k0 * Ncols;
        float e[8];
        e[0] = pk0[n0];                 e[1] = pk0[Ncols + n0];
        e[2] = pk0[8 * Ncols + n0];     e[3] = pk0[9 * Ncols + n0];
        e[4] = pk0[n0 + 8];             e[5] = pk0[Ncols + n0 + 8];
        e[6] = pk0[8 * Ncols + n0 + 8]; e[7] = pk0[9 * Ncols + n0 + 8];
        float h[8], l[8];
#pragma unroll
        for (int i = 0; i < 8; i++) split2(e[i], h[i], l[i]);
        dhi[idx] = make_uint4(pk(h[0], h[1]), pk(h[2], h[3]),
                              pk(h[4], h[5]), pk(h[6], h[7]));
        dlo[idx] = make_uint4(pk(l[0], l[1]), pk(l[2], l[3]),
                              pk(l[4], l[5]), pk(l[6], l[7]));
    }
}

// ---------------------------------------------------------------------------
// GEMM: BM=128, BN=128, BK=32, 3-stage cp.async, 8 warps (2x4), warp 64x32.
// MODE 0: fp32 store.  MODE 1: emit A-frags.  MODE 2: emit B-frags (smem
// transpose). RELU applied before frag emission / store when set.
// grid: x = nbX*batch (bx = x%nbX, bz = x/nbX), y = M/128.
// ---------------------------------------------------------------------------
template <int MODE, int RELU>
__global__ __launch_bounds__(256, 2)
void gemm_bf16x3(const uint4* __restrict__ Ah, const uint4* __restrict__ Al,
                 const uint4* __restrict__ Bh, const uint4* __restrict__ Bl,
                 float* __restrict__ C, uint4* __restrict__ FH,
                 uint4* __restrict__ FL, int Ncols, int K, int nbX,
                 size_t sBu4, size_t sCf, int mbPerBatch, size_t sFu4) {
    extern __shared__ __align__(128) char sm[];
    const int tid = threadIdx.x;
    const int lane = tid & 31;
    const int wid = tid >> 5;
    const int wm = wid >> 2;
    const int wn = wid & 3;
    const int bx = blockIdx.x % nbX;
    const int bz = blockIdx.x / nbX;
    const int by = blockIdx.y;

    Bh += (size_t)bz * sBu4;
    Bl += (size_t)bz * sBu4;

    const int nc2 = K >> 5;
    const int nkc = K >> 4;
    const int nnb = Ncols >> 7;
    const uint32_t sbase = smem_u32(sm);

    float acc[4][4][4];
#pragma unroll
    for (int i = 0; i < 4; i++)
#pragma unroll
        for (int j = 0; j < 4; j++)
#pragma unroll
            for (int r = 0; r < 4; r++) acc[i][j][r] = 0.f;

    auto issue = [&](int s, int c) {
        uint32_t sa = sbase + s * 32768 + tid * 16;
        size_t ab = ((size_t)by * nkc + (size_t)(c << 1)) * 256 + tid;
        size_t bb0 = ((size_t)(c << 1) * nnb + bx) * 256 + tid;
        size_t bb1 = bb0 + (size_t)nnb * 256;
        cpa16(sa,         Ah + ab);
        cpa16(sa + 4096,  Ah + ab + 256);
        cpa16(sa + 8192,  Al + ab);
        cpa16(sa + 12288, Al + ab + 256);
        cpa16(sa + 16384, Bh + bb0);
        cpa16(sa + 20480, Bh + bb1);
        cpa16(sa + 24576, Bl + bb0);
        cpa16(sa + 28672, Bl + bb1);
    };

    issue(0, 0); CP_COMMIT();
    issue(1, 1); CP_COMMIT();

    for (int c = 0; c < nc2; ++c) {
        int s = c % 3;
        CP_WAIT1();
        __syncthreads();
        const char* st = sm + s * 32768;
#pragma unroll
        for (int kk = 0; kk < 2; ++kk) {
            const uint4* sAh = (const uint4*)(st + kk * 4096);
            const uint4* sAl = (const uint4*)(st + 8192 + kk * 4096);
            const uint4* sBh = (const uint4*)(st + 16384 + kk * 4096);
            const uint4* sBl = (const uint4*)(st + 24576 + kk * 4096);
            uint4 fAh[4], fAl[4], fBh[2], fBl[2];
#pragma unroll
            for (int i = 0; i < 4; i++) {
                fAh[i] = sAh[(wm * 4 + i) * 32 + lane];
                fAl[i] = sAl[(wm * 4 + i) * 32 + lane];
            }
#pragma unroll
            for (int q = 0; q < 2; q++) {
                fBh[q] = sBh[(wn * 2 + q) * 32 + lane];
                fBl[q] = sBl[(wn * 2 + q) * 32 + lane];
            }
#pragma unroll
            for (int i = 0; i < 4; i++) {
#pragma unroll
                for (int j = 0; j < 4; j++) {
                    int q = j >> 1;
                    uint32_t bh0 = (j & 1) ? fBh[q].z : fBh[q].x;
                    uint32_t bh1 = (j & 1) ? fBh[q].w : fBh[q].y;
                    uint32_t bl0 = (j & 1) ? fBl[q].z : fBl[q].x;
                    uint32_t bl1 = (j & 1) ? fBl[q].w : fBl[q].y;
                    mma16816(acc[i][j], fAh[i], bh0, bh1);
                    mma16816(acc[i][j], fAl[i], bh0, bh1);
                    mma16816(acc[i][j], fAh[i], bl0, bl1);
                }
            }
        }
        if (c + 2 < nc2) issue((c + 2) % 3, c + 2);
        CP_COMMIT();
    }

    if (RELU) {
#pragma unroll
        for (int i = 0; i < 4; i++)
#pragma unroll
            for (int j = 0; j < 4; j++)
#pragma unroll
                for (int r = 0; r < 4; r++) acc[i][j][r] = fmaxf(acc[i][j][r], 0.f);
    }

    if (MODE == 0) {
        float* Cb = C + (size_t)bz * sCf;
        const int row0 = by * 128 + wm * 64 + (lane >> 2);
        const int colb = bx * 128 + wn * 32 + (lane & 3) * 2;
#pragma unroll
        for (int i = 0; i < 4; i++)
#pragma unroll
            for (int j = 0; j < 4; j++) {
                int r = row0 + i * 16;
                int col = colb + j * 8;
                *reinterpret_cast<float2*>(Cb + (size_t)r * Ncols + col) =
                    make_float2(acc[i][j][0], acc[i][j][1]);
                *reinterpret_cast<float2*>(Cb + (size_t)(r + 8) * Ncols + col) =
                    make_float2(acc[i][j][2], acc[i][j][3]);
            }
    } else if (MODE == 1) {
        // emit A-frags for next GEMM (C-frag layout == A-frag layout)
        const int nkNext = Ncols >> 4;
        const size_t mb = (size_t)bz * mbPerBatch + by;
#pragma unroll
        for (int i = 0; i < 4; i++)
#pragma unroll
            for (int jp = 0; jp < 2; jp++) {
                float h[8], l[8];
#pragma unroll
                for (int r = 0; r < 4; r++) {
                    split2(acc[i][2 * jp][r], h[r], l[r]);
                    split2(acc[i][2 * jp + 1][r], h[4 + r], l[4 + r]);
                }
                int kcg = bx * 8 + wn * 2 + jp;
                size_t di = (mb * nkNext + kcg) * 256 + (wm * 4 + i) * 32 + lane;
                FH[di] = make_uint4(pk(h[0], h[1]), pk(h[2], h[3]),
                                    pk(h[4], h[5]), pk(h[6], h[7]));
                FL[di] = make_uint4(pk(l[0], l[1]), pk(l[2], l[3]),
                                    pk(l[4], l[5]), pk(l[6], l[7]));
            }
    } else {
        // MODE 2: emit B-frags for next GEMM via smem transpose.
        // This tile = k-range [by*128..] x n-range [bx*128..] of next B.
        // Folded batch: 32 row-panels (4096 rows) per batch.
        CP_WAIT0();
        __syncthreads();
        float* sf = (float*)sm;  // 128 x 132 fp32
        const int r0 = wm * 64 + (lane >> 2);
        const int c0 = wn * 32 + (lane & 3) * 2;
#pragma unroll
        for (int i = 0; i < 4; i++)
#pragma unroll
            for (int j = 0; j < 4; j++) {
                int rr = r0 + i * 16, cc = c0 + j * 8;
                sf[rr * 132 + cc] = acc[i][j][0];
                sf[rr * 132 + cc + 1] = acc[i][j][1];
                sf[(rr + 8) * 132 + cc] = acc[i][j][2];
                sf[(rr + 8) * 132 + cc + 1] = acc[i][j][3];
            }
        __syncthreads();
        const int batchO = by >> 5;
        const int mbLoc = by & 31;
        const int jj = tid >> 5;
        const int ln = tid & 31;
        const int n0 = 16 * jj + (ln >> 2);
        const int k0b = (ln & 3) * 2;
#pragma unroll
        for (int kb = 0; kb < 8; kb++) {
            int k0 = kb * 16 + k0b;
            float e[8];
            e[0] = sf[k0 * 132 + n0];
            e[1] = sf[(k0 + 1) * 132 + n0];
            e[2] = sf[(k0 + 8) * 132 + n0];
            e[3] = sf[(k0 + 9) * 132 + n0];
            e[4] = sf[k0 * 132 + n0 + 8];
            e[5] = sf[(k0 + 1) * 132 + n0 + 8];
            e[6] = sf[(k0 + 8) * 132 + n0 + 8];
            e[7] = sf[(k0 + 9) * 132 + n0 + 8];
            float h[8], l[8];
#pragma unroll
            for (int r = 0; r < 8; r++) split2(e[r], h[r], l[r]);
            int kc = mbLoc * 8 + kb;
            size_t di = (size_t)batchO * sFu4 + ((size_t)kc * nbX + bx) * 256 + tid;
            FH[di] = make_uint4(pk(h[0], h[1]), pk(h[2], h[3]),
                                pk(h[4], h[5]), pk(h[6], h[7]));
            FL[di] = make_uint4(pk(l[0], l[1]), pk(l[2], l[3]),
                                pk(l[4], l[5]), pk(l[6], l[7]));
        }
    }
}

// ---------------------------------------------------------------------------
template <int MODE, int RELU>
static void launch_gemm(int M, int Ncols, int K,
                        const uint4* Ah, const uint4* Al,
                        const uint4* Bh, const uint4* Bl,
                        float* C, uint4* FH, uint4* FL,
                        int batch, size_t sBu4, size_t sCf,
                        int mbPerBatch, size_t sFu4) {
    int nbX = Ncols / 128;
    dim3 g(nbX * batch, M / 128);
    int smem = 3 * 32768;
    cudaFuncSetAttribute(gemm_bf16x3<MODE, RELU>,
                         cudaFuncAttributeMaxDynamicSharedMemorySize, smem);
    gemm_bf16x3<MODE, RELU><<<g, 256, smem>>>(Ah, Al, Bh, Bl, C, FH, FL, Ncols,
                                              K, nbX, sBu4, sCf, mbPerBatch,
                                              sFu4);
}

extern "C" void kernel_launch(void* const* d_in, const int* in_sizes, int n_in,
                              void* d_out, int out_size) {
    const float* x   = (const float*)d_in[0];  // [B, N, 256]
    const float* adj = (const float*)d_in[1];
    const float* S   = (const float*)d_in[2];
    const float* W1  = (const float*)d_in[3];  // [256, 512]
    const float* W2  = (const float*)d_in[4];  // [512, 1024]
    const float* W3  = (const float*)d_in[5];  // [1024, 256]
    float* out = (float*)d_out;                // [B, N, 256]

    uint4 *AwH, *AwL, *FaH, *FaL, *FbH, *FbL, *WH, *WL;
    cudaGetSymbolAddress((void**)&AwH, g_AwH);
    cudaGetSymbolAddress((void**)&AwL, g_AwL);
    cudaGetSymbolAddress((void**)&FaH, g_FaH);
    cudaGetSymbolAddress((void**)&FaL, g_FaL);
    cudaGetSymbolAddress((void**)&FbH, g_FbH);
    cudaGetSymbolAddress((void**)&FbL, g_FbL);
    cudaGetSymbolAddress((void**)&WH, g_WH);
    cudaGetSymbolAddress((void**)&WL, g_WL);

    const size_t sX  = (size_t)NN * 256 / 8;   // per-batch u4 strides
    const size_t sH1 = (size_t)NN * 512 / 8;
    const size_t sS3 = (size_t)NN * 256 / 8;

    // One-time preps: Aw = adj.*S (A-frags); x (B-frags); W1/W2/W3 (B-frags)
    prep_A<<<2048, 256>>>(adj, S, AwH, AwL, NN, NN);
    prep_B<<<dim3(512, 1, BB), 256>>>(x, FbH, FbL, NN, 256,
                                      (size_t)NN * 256, sX);
    prep_B<<<64, 256>>>(W1, WH, WL, 256, 512, 0, 0);
    prep_B<<<256, 256>>>(W2, WH + 16384, WL + 16384, 512, 1024, 0, 0);
    prep_B<<<128, 256>>>(W3, WH + 81920, WL + 81920, 1024, 256, 0, 0);

    // G1: t1 = Aw @ x  [4096,256] per batch -> A-frags (Fa)
    launch_gemm<1, 0>(NN, 256, NN, AwH, AwL, FbH, FbL, nullptr, FaH, FaL,
                      BB, sX, 0, NN / 128, 0);
    // G2: h1 = relu(t1 @ W1)  [32768,512] -> B-frags (Fb, per-batch sH1)
    launch_gemm<2, 1>(BB * NN, 512, 256, FaH, FaL, WH, WL, nullptr, FbH, FbL,
                      1, 0, 0, 0, sH1);
    // G3: t2 = Aw @ h1  [4096,512] per batch -> A-frags (Fa)
    launch_gemm<1, 0>(NN, 512, NN, AwH, AwL, FbH, FbL, nullptr, FaH, FaL,
                      BB, sH1, 0, NN / 128, 0);
    // G4: h2 = relu(t2 @ W2)  [32768,1024] -> A-frags (Fb)
    launch_gemm<1, 1>(BB * NN, 1024, 512, FaH, FaL, WH + 16384, WL + 16384,
                      nullptr, FbH, FbL, 1, 0, 0, 0, 0);
    // G5: s3 = h2 @ W3  [32768,256] -> B-frags (Fa, per-batch sS3)
    launch_gemm<2, 0>(BB * NN, 256, 1024, FbH, FbL, WH + 81920, WL + 81920,
                      nullptr, FaH, FaL, 1, 0, 0, 0, sS3);
    // G6: out = Aw @ s3  [4096,256] per batch -> fp32
    launch_gemm<0, 0>(NN, 256, NN, AwH, AwL, FaH, FaL, out, nullptr, nullptr,
                      BB, sS3, (size_t)NN * 256, 0, 0);
}

// round 7
// speedup vs baseline: 7.0597x; 1.2782x over previous
#include <cuda_runtime.h>
#include <cuda_fp16.h>
#include <cstdint>

// GCN — reassociated 3-layer GCN, fp16-split mma.sync, globally scaled.
// x' = x/64 (relu is positively homogeneous; final output *= 64).
// t1=Aw@x'; h1=relu(t1@W1); t2=Aw@h1; h2=relu(t2@W2); s3=h2@W3; out=64*Aw@s3.
// Aw GEMMs: A = fp16 hi only, 2 products (AhBh + AhBl).
// W  GEMMs: A = fp16 hi/lo, 3 products (AhBh + AlBh + AhBl).

#define NN 4096
#define BB 4
#define XSCALE (1.0f / 64.0f)
#define OSCALE 64.0f

// Fragment-tiled storage: A blocks 128m x 16k = 256 uint4 (block = mb*nkc+kc),
// B blocks 16k x 128n = 256 uint4 (block = kc*nnb+nb).
__device__ uint4 g_AwH[(size_t)NN * NN / 8];
__device__ uint4 g_FaH[(size_t)BB * NN * 1024 / 8];  // ping
__device__ uint4 g_FaL[(size_t)BB * NN * 1024 / 8];
__device__ uint4 g_FbH[(size_t)BB * NN * 1024 / 8];  // pong
__device__ uint4 g_FbL[(size_t)BB * NN * 1024 / 8];
__device__ uint4 g_WH[114688];  // W1@0, W2@16384, W3@81920
__device__ uint4 g_WL[114688];

// ---------------------------------------------------------------------------
__device__ __forceinline__ uint32_t smem_u32(const void* p) {
    uint32_t a;
    asm("{ .reg .u64 t; cvta.to.shared.u64 t, %1; cvt.u32.u64 %0, t; }"
        : "=r"(a) : "l"(p));
    return a;
}
__device__ __forceinline__ uint32_t pk(float a, float b) {
    __half2 t = __floats2half2_rn(a, b);
    return *reinterpret_cast<uint32_t*>(&t);
}
__device__ __forceinline__ void split2(float v, float& h, float& l) {
    h = __half2float(__float2half_rn(v));
    l = v - h;
}
__device__ __forceinline__ void cpa16(uint32_t saddr, const void* gaddr) {
    asm volatile("cp.async.cg.shared.global [%0], [%1], 16;"
                 :: "r"(saddr), "l"(gaddr));
}
#define CP_COMMIT() asm volatile("cp.async.commit_group;" ::: "memory")
#define CP_WAIT1()  asm volatile("cp.async.wait_group 1;" ::: "memory")
#define CP_WAIT0()  asm volatile("cp.async.wait_group 0;" ::: "memory")

__device__ __forceinline__ void mma16816(float* c, const uint4& a,
                                         uint32_t b0, uint32_t b1) {
    asm volatile(
        "mma.sync.aligned.m16n8k16.row.col.f32.f16.f16.f32 "
        "{%0,%1,%2,%3},{%4,%5,%6,%7},{%8,%9},{%0,%1,%2,%3};"
        : "+f"(c[0]), "+f"(c[1]), "+f"(c[2]), "+f"(c[3])
        : "r"(a.x), "r"(a.y), "r"(a.z), "r"(a.w), "r"(b0), "r"(b1));
}

// ---------------------------------------------------------------------------
// prep_A: src [M,K] f32 (optional elementwise mul) -> A-frag hi (lo if dlo)
// ---------------------------------------------------------------------------
__global__ void prep_A(const float* __restrict__ src,
                       const float* __restrict__ mul,
                       uint4* __restrict__ dhi, uint4* __restrict__ dlo,
                       int M, int K) {
    size_t total = ((size_t)M * K) >> 3;
    int nkc = K >> 4;
    for (size_t idx = (size_t)blockIdx.x * blockDim.x + threadIdx.x; idx < total;
         idx += (size_t)gridDim.x * blockDim.x) {
        int lane = (int)(idx & 31);
        int mt = (int)((idx >> 5) & 7);
        size_t blk = idx >> 8;
        int kc = (int)(blk % nkc);
        size_t mb = blk / nkc;
        int r0 = (int)(mb * 128) + mt * 16 + (lane >> 2);
        int c0 = kc * 16 + (lane & 3) * 2;
        const float* p0 = src + (size_t)r0 * K + c0;
        const float* p1 = p0 + (size_t)8 * K;
        float e[8];
        e[0] = p0[0]; e[1] = p0[1]; e[2] = p1[0]; e[3] = p1[1];
        e[4] = p0[8]; e[5] = p0[9]; e[6] = p1[8]; e[7] = p1[9];
        if (mul) {
            const float* q0 = mul + (size_t)r0 * K + c0;
            const float* q1 = q0 + (size_t)8 * K;
            e[0] *= q0[0]; e[1] *= q0[1]; e[2] *= q1[0]; e[3] *= q1[1];
            e[4] *= q0[8]; e[5] *= q0[9]; e[6] *= q1[8]; e[7] *= q1[9];
        }
        float h[8], l[8];
#pragma unroll
        for (int i = 0; i < 8; i++) split2(e[i], h[i], l[i]);
        dhi[idx] = make_uint4(pk(h[0], h[1]), pk(h[2], h[3]),
                              pk(h[4], h[5]), pk(h[6], h[7]));
        if (dlo)
            dlo[idx] = make_uint4(pk(l[0], l[1]), pk(l[2], l[3]),
                                  pk(l[4], l[5]), pk(l[6], l[7]));
    }
}

// ---------------------------------------------------------------------------
// prep_B: src [K,Ncols] f32 row-major * scale -> B-frag hi/lo (batch via z)
// ---------------------------------------------------------------------------
__global__ void prep_B(const float* __restrict__ src,
                       uint4* __restrict__ dhi, uint4* __restrict__ dlo,
                       int K, int Ncols, size_t sSrc, size_t sDst,
                       float scale) {
    src += (size_t)blockIdx.z * sSrc;
    dhi += (size_t)blockIdx.z * sDst;
    dlo += (size_t)blockIdx.z * sDst;
    size_t total = ((size_t)K * Ncols) >> 3;
    int nnb = Ncols >> 7;
    for (size_t idx = (size_t)blockIdx.x * blockDim.x + threadIdx.x; idx < total;
         idx += (size_t)gridDim.x * blockDim.x) {
        int lane = (int)(idx & 31);
        int j = (int)((idx >> 5) & 7);
        size_t blk = idx >> 8;
        int nb = (int)(blk % nnb);
        int kc = (int)(blk / nnb);
        int n0 = nb * 128 + (2 * j) * 8 + (lane >> 2);
        int k0 = kc * 16 + (lane & 3) * 2;
        const float* pk0 = src + (size_t)k0 * Ncols;
        float e[8];
        e[0] = pk0[n0];                 e[1] = pk0[Ncols + n0];
        e[2] = pk0[8 * Ncols + n0];     e[3] = pk0[9 * Ncols + n0];
        e[4] = pk0[n0 + 8];             e[5] = pk0[Ncols + n0 + 8];
        e[6] = pk0[8 * Ncols + n0 + 8]; e[7] = pk0[9 * Ncols + n0 + 8];
        float h[8], l[8];
#pragma unroll
        for (int i = 0; i < 8; i++) split2(e[i] * scale, h[i], l[i]);
        dhi[idx] = make_uint4(pk(h[0], h[1]), pk(h[2], h[3]),
                              pk(h[4], h[5]), pk(h[6], h[7]));
        dlo[idx] = make_uint4(pk(l[0], l[1]), pk(l[2], l[3]),
                              pk(l[4], l[5]), pk(l[6], l[7]));
    }
}

// ---------------------------------------------------------------------------
// GEMM: BM=128, BN=128, BK=32, 3-stage cp.async, 8 warps (2x4), warp 64x32.
// MODE 0: fp32 store (scaled by outScale).  MODE 1: emit A-frags.
// MODE 2: emit B-frags (smem transpose).  RELU before emission.
// ALO: A has lo part (3 products) else 2 products (AhBh + AhBl).
// grid: x = nbX*batch (bx = x%nbX, bz = x/nbX), y = M/128.
// ---------------------------------------------------------------------------
template <int MODE, int RELU, int ALO>
__global__ __launch_bounds__(256, 2)
void gemm_f16(const uint4* __restrict__ Ah, const uint4* __restrict__ Al,
              const uint4* __restrict__ Bh, const uint4* __restrict__ Bl,
              float* __restrict__ C, uint4* __restrict__ FH,
              uint4* __restrict__ FL, int Ncols, int K, int nbX,
              size_t sBu4, size_t sCf, int mbPerBatch, size_t sFu4,
              float outScale) {
    extern __shared__ __align__(128) char sm[];
    const int tid = threadIdx.x;
    const int lane = tid & 31;
    const int wid = tid >> 5;
    const int wm = wid >> 2;
    const int wn = wid & 3;
    const int bx = blockIdx.x % nbX;
    const int bz = blockIdx.x / nbX;
    const int by = blockIdx.y;

    Bh += (size_t)bz * sBu4;
    Bl += (size_t)bz * sBu4;

    const int nc2 = K >> 5;
    const int nkc = K >> 4;
    const int nnb = Ncols >> 7;
    const uint32_t sbase = smem_u32(sm);

    float acc[4][4][4];
#pragma unroll
    for (int i = 0; i < 4; i++)
#pragma unroll
        for (int j = 0; j < 4; j++)
#pragma unroll
            for (int r = 0; r < 4; r++) acc[i][j][r] = 0.f;

    auto issue = [&](int s, int c) {
        uint32_t sa = sbase + s * 32768 + tid * 16;
        size_t ab = ((size_t)by * nkc + (size_t)(c << 1)) * 256 + tid;
        size_t bb0 = ((size_t)(c << 1) * nnb + bx) * 256 + tid;
        size_t bb1 = bb0 + (size_t)nnb * 256;
        cpa16(sa,         Ah + ab);
        cpa16(sa + 4096,  Ah + ab + 256);
        if (ALO) {
            cpa16(sa + 8192,  Al + ab);
            cpa16(sa + 12288, Al + ab + 256);
        }
        cpa16(sa + 16384, Bh + bb0);
        cpa16(sa + 20480, Bh + bb1);
        cpa16(sa + 24576, Bl + bb0);
        cpa16(sa + 28672, Bl + bb1);
    };

    issue(0, 0); CP_COMMIT();
    issue(1, 1); CP_COMMIT();

    for (int c = 0; c < nc2; ++c) {
        int s = c % 3;
        CP_WAIT1();
        __syncthreads();
        const char* st = sm + s * 32768;
#pragma unroll
        for (int kk = 0; kk < 2; ++kk) {
            const uint4* sAh = (const uint4*)(st + kk * 4096);
            const uint4* sAl = (const uint4*)(st + 8192 + kk * 4096);
            const uint4* sBh = (const uint4*)(st + 16384 + kk * 4096);
            const uint4* sBl = (const uint4*)(st + 24576 + kk * 4096);
            uint4 fAh[4], fAl[4], fBh[2], fBl[2];
#pragma unroll
            for (int i = 0; i < 4; i++) {
                fAh[i] = sAh[(wm * 4 + i) * 32 + lane];
                if (ALO) fAl[i] = sAl[(wm * 4 + i) * 32 + lane];
            }
#pragma unroll
            for (int q = 0; q < 2; q++) {
                fBh[q] = sBh[(wn * 2 + q) * 32 + lane];
                fBl[q] = sBl[(wn * 2 + q) * 32 + lane];
            }
#pragma unroll
            for (int i = 0; i < 4; i++) {
#pragma unroll
                for (int j = 0; j < 4; j++) {
                    int q = j >> 1;
                    uint32_t bh0 = (j & 1) ? fBh[q].z : fBh[q].x;
                    uint32_t bh1 = (j & 1) ? fBh[q].w : fBh[q].y;
                    uint32_t bl0 = (j & 1) ? fBl[q].z : fBl[q].x;
                    uint32_t bl1 = (j & 1) ? fBl[q].w : fBl[q].y;
                    mma16816(acc[i][j], fAh[i], bh0, bh1);
                    if (ALO) mma16816(acc[i][j], fAl[i], bh0, bh1);
                    mma16816(acc[i][j], fAh[i], bl0, bl1);
                }
            }
        }
        if (c + 2 < nc2) issue((c + 2) % 3, c + 2);
        CP_COMMIT();
    }

    if (RELU) {
#pragma unroll
        for (int i = 0; i < 4; i++)
#pragma unroll
            for (int j = 0; j < 4; j++)
#pragma unroll
                for (int r = 0; r < 4; r++) acc[i][j][r] = fmaxf(acc[i][j][r], 0.f);
    }

    if (MODE == 0) {
        float* Cb = C + (size_t)bz * sCf;
        const int row0 = by * 128 + wm * 64 + (lane >> 2);
        const int colb = bx * 128 + wn * 32 + (lane & 3) * 2;
#pragma unroll
        for (int i = 0; i < 4; i++)
#pragma unroll
            for (int j = 0; j < 4; j++) {
                int r = row0 + i * 16;
                int col = colb + j * 8;
                *reinterpret_cast<float2*>(Cb + (size_t)r * Ncols + col) =
                    make_float2(acc[i][j][0] * outScale, acc[i][j][1] * outScale);
                *reinterpret_cast<float2*>(Cb + (size_t)(r + 8) * Ncols + col) =
                    make_float2(acc[i][j][2] * outScale, acc[i][j][3] * outScale);
            }
    } else if (MODE == 1) {
        // emit A-frags for next GEMM (C-frag layout == A-frag layout)
        const int nkNext = Ncols >> 4;
        const size_t mb = (size_t)bz * mbPerBatch + by;
#pragma unroll
        for (int i = 0; i < 4; i++)
#pragma unroll
            for (int jp = 0; jp < 2; jp++) {
                float h[8], l[8];
#pragma unroll
                for (int r = 0; r < 4; r++) {
                    split2(acc[i][2 * jp][r], h[r], l[r]);
                    split2(acc[i][2 * jp + 1][r], h[4 + r], l[4 + r]);
                }
                int kcg = bx * 8 + wn * 2 + jp;
                size_t di = (mb * nkNext + kcg) * 256 + (wm * 4 + i) * 32 + lane;
                FH[di] = make_uint4(pk(h[0], h[1]), pk(h[2], h[3]),
                                    pk(h[4], h[5]), pk(h[6], h[7]));
                FL[di] = make_uint4(pk(l[0], l[1]), pk(l[2], l[3]),
                                    pk(l[4], l[5]), pk(l[6], l[7]));
            }
    } else {
        // MODE 2: emit B-frags for next GEMM via smem transpose.
        CP_WAIT0();
        __syncthreads();
        float* sf = (float*)sm;  // 128 x 132 fp32
        const int r0 = wm * 64 + (lane >> 2);
        const int c0 = wn * 32 + (lane & 3) * 2;
#pragma unroll
        for (int i = 0; i < 4; i++)
#pragma unroll
            for (int j = 0; j < 4; j++) {
                int rr = r0 + i * 16, cc = c0 + j * 8;
                sf[rr * 132 + cc] = acc[i][j][0];
                sf[rr * 132 + cc + 1] = acc[i][j][1];
                sf[(rr + 8) * 132 + cc] = acc[i][j][2];
                sf[(rr + 8) * 132 + cc + 1] = acc[i][j][3];
            }
        __syncthreads();
        const int batchO = by >> 5;
        const int mbLoc = by & 31;
        const int jj = tid >> 5;
        const int ln = tid & 31;
        const int n0 = 16 * jj + (ln >> 2);
        const int k0b = (ln & 3) * 2;
#pragma unroll
        for (int kb = 0; kb < 8; kb++) {
            int k0 = kb * 16 + k0b;
            float e[8];
            e[0] = sf[k0 * 132 + n0];
            e[1] = sf[(k0 + 1) * 132 + n0];
            e[2] = sf[(k0 + 8) * 132 + n0];
            e[3] = sf[(k0 + 9) * 132 + n0];
            e[4] = sf[k0 * 132 + n0 + 8];
            e[5] = sf[(k0 + 1) * 132 + n0 + 8];
            e[6] = sf[(k0 + 8) * 132 + n0 + 8];
            e[7] = sf[(k0 + 9) * 132 + n0 + 8];
            float h[8], l[8];
#pragma unroll
            for (int r = 0; r < 8; r++) split2(e[r], h[r], l[r]);
            int kc = mbLoc * 8 + kb;
            size_t di = (size_t)batchO * sFu4 + ((size_t)kc * nbX + bx) * 256 + tid;
            FH[di] = make_uint4(pk(h[0], h[1]), pk(h[2], h[3]),
                                pk(h[4], h[5]), pk(h[6], h[7]));
            FL[di] = make_uint4(pk(l[0], l[1]), pk(l[2], l[3]),
                                pk(l[4], l[5]), pk(l[6], l[7]));
        }
    }
}

// ---------------------------------------------------------------------------
template <int MODE, int RELU, int ALO>
static void launch_gemm(int M, int Ncols, int K,
                        const uint4* Ah, const uint4* Al,
                        const uint4* Bh, const uint4* Bl,
                        float* C, uint4* FH, uint4* FL,
                        int batch, size_t sBu4, size_t sCf,
                        int mbPerBatch, size_t sFu4, float outScale) {
    int nbX = Ncols / 128;
    dim3 g(nbX * batch, M / 128);
    int smem = 3 * 32768;
    cudaFuncSetAttribute(gemm_f16<MODE, RELU, ALO>,
                         cudaFuncAttributeMaxDynamicSharedMemorySize, smem);
    gemm_f16<MODE, RELU, ALO><<<g, 256, smem>>>(Ah, Al, Bh, Bl, C, FH, FL,
                                                Ncols, K, nbX, sBu4, sCf,
                                                mbPerBatch, sFu4, outScale);
}

extern "C" void kernel_launch(void* const* d_in, const int* in_sizes, int n_in,
                              void* d_out, int out_size) {
    const float* x   = (const float*)d_in[0];  // [B, N, 256]
    const float* adj = (const float*)d_in[1];
    const float* S   = (const float*)d_in[2];
    const float* W1  = (const float*)d_in[3];  // [256, 512]
    const float* W2  = (const float*)d_in[4];  // [512, 1024]
    const float* W3  = (const float*)d_in[5];  // [1024, 256]
    float* out = (float*)d_out;                // [B, N, 256]

    uint4 *AwH, *FaH, *FaL, *FbH, *FbL, *WH, *WL;
    cudaGetSymbolAddress((void**)&AwH, g_AwH);
    cudaGetSymbolAddress((void**)&FaH, g_FaH);
    cudaGetSymbolAddress((void**)&FaL, g_FaL);
    cudaGetSymbolAddress((void**)&FbH, g_FbH);
    cudaGetSymbolAddress((void**)&FbL, g_FbL);
    cudaGetSymbolAddress((void**)&WH, g_WH);
    cudaGetSymbolAddress((void**)&WL, g_WL);

    const size_t sX  = (size_t)NN * 256 / 8;   // per-batch u4 strides
    const size_t sH1 = (size_t)NN * 512 / 8;
    const size_t sS3 = (size_t)NN * 256 / 8;

    // One-time preps: Aw = adj.*S (A-frags hi only); x/64 (B-frags); W (B-frags)
    prep_A<<<2048, 256>>>(adj, S, AwH, nullptr, NN, NN);
    prep_B<<<dim3(512, 1, BB), 256>>>(x, FbH, FbL, NN, 256,
                                      (size_t)NN * 256, sX, XSCALE);
    prep_B<<<64, 256>>>(W1, WH, WL, 256, 512, 0, 0, 1.0f);
    prep_B<<<256, 256>>>(W2, WH + 16384, WL + 16384, 512, 1024, 0, 0, 1.0f);
    prep_B<<<128, 256>>>(W3, WH + 81920, WL + 81920, 1024, 256, 0, 0, 1.0f);

    // G1: t1 = Aw @ x' -> A-frags (Fa).  2-product.
    launch_gemm<1, 0, 0>(NN, 256, NN, AwH, nullptr, FbH, FbL, nullptr,
                         FaH, FaL, BB, sX, 0, NN / 128, 0, 1.0f);
    // G2: h1 = relu(t1 @ W1) -> B-frags (Fb).  3-product.
    launch_gemm<2, 1, 1>(BB * NN, 512, 256, FaH, FaL, WH, WL, nullptr,
                         FbH, FbL, 1, 0, 0, 0, sH1, 1.0f);
    // G3: t2 = Aw @ h1 -> A-frags (Fa).  2-product.
    launch_gemm<1, 0, 0>(NN, 512, NN, AwH, nullptr, FbH, FbL, nullptr,
                         FaH, FaL, BB, sH1, 0, NN / 128, 0, 1.0f);
    // G4: h2 = relu(t2 @ W2) -> A-frags (Fb).  3-product.
    launch_gemm<1, 1, 1>(BB * NN, 1024, 512, FaH, FaL, WH + 16384, WL + 16384,
                         nullptr, FbH, FbL, 1, 0, 0, 0, 0, 1.0f);
    // G5: s3 = h2 @ W3 -> B-frags (Fa).  3-product.
    launch_gemm<2, 0, 1>(BB * NN, 256, 1024, FbH, FbL, WH + 81920, WL + 81920,
                         nullptr, FaH, FaL, 1, 0, 0, 0, sS3, 1.0f);
    // G6: out = OSCALE * (Aw @ s3) -> fp32.  2-product.
    launch_gemm<0, 0, 0>(NN, 256, NN, AwH, nullptr, FaH, FaL, out,
                         nullptr, nullptr, BB, sS3, (size_t)NN * 256, 0, 0,
                         OSCALE);
}

// round 8
// speedup vs baseline: 8.6382x; 1.2236x over previous
#include <cuda_runtime.h>
#include <cuda_fp16.h>
#include <cstdint>

// GCN — reassociated 3-layer GCN, fp16-split mma.sync, globally scaled.
// x' = x/64; out *= 64 (relu positively homogeneous).
// t1=Aw@x'(2p); h1=relu(t1@W1)(3p,hi-out); t2=Aw@h1(1p); h2=relu(t2@W2)(3p,hi-out);
// s3=h2@W3(2p); out=64*Aw@s3(2p).

#define NN 4096
#define BB 4
#define XSCALE (1.0f / 64.0f)
#define OSCALE 64.0f

// Fragment-tiled storage: A blocks 128m x 16k = 256 uint4 (block = mb*nkc+kc),
// B blocks 16k x 128n = 256 uint4 (block = kc*nnb+nb).
__device__ uint4 g_AwH[(size_t)NN * NN / 8];
__device__ uint4 g_FaH[(size_t)BB * NN * 1024 / 8];  // ping
__device__ uint4 g_FaL[(size_t)BB * NN * 1024 / 8];
__device__ uint4 g_FbH[(size_t)BB * NN * 1024 / 8];  // pong
__device__ uint4 g_FbL[(size_t)BB * NN * 1024 / 8];
__device__ uint4 g_WH[114688];  // W1@0, W2@16384, W3@81920
__device__ uint4 g_WL[114688];

// ---------------------------------------------------------------------------
__device__ __forceinline__ uint32_t smem_u32(const void* p) {
    uint32_t a;
    asm("{ .reg .u64 t; cvta.to.shared.u64 t, %1; cvt.u32.u64 %0, t; }"
        : "=r"(a) : "l"(p));
    return a;
}
__device__ __forceinline__ uint32_t pk(float a, float b) {
    __half2 t = __floats2half2_rn(a, b);
    return *reinterpret_cast<uint32_t*>(&t);
}
__device__ __forceinline__ void split2(float v, float& h, float& l) {
    h = __half2float(__float2half_rn(v));
    l = v - h;
}
__device__ __forceinline__ void cpa16(uint32_t saddr, const void* gaddr) {
    asm volatile("cp.async.cg.shared.global [%0], [%1], 16;"
                 :: "r"(saddr), "l"(gaddr));
}
#define CP_COMMIT() asm volatile("cp.async.commit_group;" ::: "memory")
#define CP_WAIT1()  asm volatile("cp.async.wait_group 1;" ::: "memory")
#define CP_WAIT0()  asm volatile("cp.async.wait_group 0;" ::: "memory")

__device__ __forceinline__ void mma16816(float* c, const uint4& a,
                                         uint32_t b0, uint32_t b1) {
    asm volatile(
        "mma.sync.aligned.m16n8k16.row.col.f32.f16.f16.f32 "
        "{%0,%1,%2,%3},{%4,%5,%6,%7},{%8,%9},{%0,%1,%2,%3};"
        : "+f"(c[0]), "+f"(c[1]), "+f"(c[2]), "+f"(c[3])
        : "r"(a.x), "r"(a.y), "r"(a.z), "r"(a.w), "r"(b0), "r"(b1));
}

// ---------------------------------------------------------------------------
// prep_A_tile: Aw = adj .* S -> A-frag hi only. Coalesced 128x64 tile stage.
// grid: (K/64, M/128), 256 threads.
// ---------------------------------------------------------------------------
__global__ __launch_bounds__(256)
void prep_A_tile(const float* __restrict__ src, const float* __restrict__ mul,
                 uint4* __restrict__ dhi, int M, int K) {
    __shared__ float smt[128][68];
    const int tid = threadIdx.x;
    const int kcb = blockIdx.x;        // 64-col tile
    const size_t mb = blockIdx.y;      // 128-row tile
    const int colBase = kcb * 64;
    const size_t rowBase = mb * 128;

    const int c4 = tid & 15;
    const int r0 = tid >> 4;
#pragma unroll
    for (int i = 0; i < 8; i++) {
        int r = r0 + i * 16;
        const float4 v = ((const float4*)(src + (rowBase + r) * K + colBase))[c4];
        const float4 s = ((const float4*)(mul + (rowBase + r) * K + colBase))[c4];
        float4 o = make_float4(v.x * s.x, v.y * s.y, v.z * s.z, v.w * s.w);
        *(float4*)&smt[r][c4 * 4] = o;
    }
    __syncthreads();

    const int lane = tid & 31;
    const int mt = tid >> 5;
    const int rr = mt * 16 + (lane >> 2);
    const int cb = (lane & 3) * 2;
    const int nkc = K >> 4;
#pragma unroll
    for (int kb = 0; kb < 4; kb++) {
        int c0 = kb * 16 + cb;
        uint4 H = make_uint4(
            pk(smt[rr][c0],     smt[rr][c0 + 1]),
            pk(smt[rr + 8][c0], smt[rr + 8][c0 + 1]),
            pk(smt[rr][c0 + 8], smt[rr][c0 + 9]),
            pk(smt[rr + 8][c0 + 8], smt[rr + 8][c0 + 9]));
        dhi[(mb * nkc + (size_t)(kcb * 4 + kb)) * 256 + tid] = H;
    }
}

// ---------------------------------------------------------------------------
// prep_B_tile: src [K,Ncols] f32 * scale -> B-frag hi (+lo). Coalesced
// 32x128 tile stage. grid: (Ncols/128, K/32, batch), 256 threads.
// ---------------------------------------------------------------------------
__global__ __launch_bounds__(256)
void prep_B_tile(const float* __restrict__ src, uint4* __restrict__ dhi,
                 uint4* __restrict__ dlo, int K, int Ncols,
                 size_t sSrc, size_t sDst, float scale) {
    __shared__ float smt[32][132];
    src += (size_t)blockIdx.z * sSrc;
    dhi += (size_t)blockIdx.z * sDst;
    if (dlo) dlo += (size_t)blockIdx.z * sDst;
    const int tid = threadIdx.x;
    const int nb = blockIdx.x;
    const int kcb = blockIdx.y;

    const int c4 = tid & 31;
    const int r0 = tid >> 5;
#pragma unroll
    for (int i = 0; i < 4; i++) {
        int r = r0 + i * 8;
        float4 v = ((const float4*)(src + (size_t)(kcb * 32 + r) * Ncols +
                                    nb * 128))[c4];
        v.x *= scale; v.y *= scale; v.z *= scale; v.w *= scale;
        *(float4*)&smt[r][c4 * 4] = v;
    }
    __syncthreads();

    const int lane = tid & 31;
    const int j = tid >> 5;
    const int n0 = j * 16 + (lane >> 2);
    const int k0b = (lane & 3) * 2;
    const int nnb = Ncols >> 7;
#pragma unroll
    for (int kk = 0; kk < 2; kk++) {
        int k0 = kk * 16 + k0b;
        float e[8];
        e[0] = smt[k0][n0];     e[1] = smt[k0 + 1][n0];
        e[2] = smt[k0 + 8][n0]; e[3] = smt[k0 + 9][n0];
        e[4] = smt[k0][n0 + 8];     e[5] = smt[k0 + 1][n0 + 8];
        e[6] = smt[k0 + 8][n0 + 8]; e[7] = smt[k0 + 9][n0 + 8];
        float h[8], l[8];
#pragma unroll
        for (int r = 0; r < 8; r++) split2(e[r], h[r], l[r]);
        size_t blk = (size_t)(kcb * 2 + kk) * nnb + nb;
        dhi[blk * 256 + tid] = make_uint4(pk(h[0], h[1]), pk(h[2], h[3]),
                                          pk(h[4], h[5]), pk(h[6], h[7]));
        if (dlo)
            dlo[blk * 256 + tid] = make_uint4(pk(l[0], l[1]), pk(l[2], l[3]),
                                              pk(l[4], l[5]), pk(l[6], l[7]));
    }
}

// ---------------------------------------------------------------------------
// GEMM: BM=128, BN=128, BK=32, 3-stage cp.async, 8 warps (2x4), warp 64x32.
// MODE 0: fp32 store (scaled).  MODE 1: emit A-frags.  MODE 2: emit B-frags.
// RELU before emission. ALO/BLO: operand lo present (products = 1+ALO+BLO).
// FLO: emit lo fragments (MODE 1/2).
// grid: x = nbX*batch (bx = x%nbX, bz = x/nbX), y = M/128.
// ---------------------------------------------------------------------------
template <int MODE, int RELU, int ALO, int BLO, int FLO>
__global__ __launch_bounds__(256, 2)
void gemm_f16(const uint4* __restrict__ Ah, const uint4* __restrict__ Al,
              const uint4* __restrict__ Bh, const uint4* __restrict__ Bl,
              float* __restrict__ C, uint4* __restrict__ FH,
              uint4* __restrict__ FL, int Ncols, int K, int nbX,
              size_t sBu4, size_t sCf, int mbPerBatch, size_t sFu4,
              float outScale) {
    extern __shared__ __align__(128) char sm[];
    const int tid = threadIdx.x;
    const int lane = tid & 31;
    const int wid = tid >> 5;
    const int wm = wid >> 2;
    const int wn = wid & 3;
    const int bx = blockIdx.x % nbX;
    const int bz = blockIdx.x / nbX;
    const int by = blockIdx.y;

    Bh += (size_t)bz * sBu4;
    if (BLO) Bl += (size_t)bz * sBu4;

    const int nc2 = K >> 5;
    const int nkc = K >> 4;
    const int nnb = Ncols >> 7;
    const uint32_t sbase = smem_u32(sm);

    float acc[4][4][4];
#pragma unroll
    for (int i = 0; i < 4; i++)
#pragma unroll
        for (int j = 0; j < 4; j++)
#pragma unroll
            for (int r = 0; r < 4; r++) acc[i][j][r] = 0.f;

    auto issue = [&](int s, int c) {
        uint32_t sa = sbase + s * 32768 + tid * 16;
        size_t ab = ((size_t)by * nkc + (size_t)(c << 1)) * 256 + tid;
        size_t bb0 = ((size_t)(c << 1) * nnb + bx) * 256 + tid;
        size_t bb1 = bb0 + (size_t)nnb * 256;
        cpa16(sa,         Ah + ab);
        cpa16(sa + 4096,  Ah + ab + 256);
        if (ALO) {
            cpa16(sa + 8192,  Al + ab);
            cpa16(sa + 12288, Al + ab + 256);
        }
        cpa16(sa + 16384, Bh + bb0);
        cpa16(sa + 20480, Bh + bb1);
        if (BLO) {
            cpa16(sa + 24576, Bl + bb0);
            cpa16(sa + 28672, Bl + bb1);
        }
    };

    issue(0, 0); CP_COMMIT();
    issue(1, 1); CP_COMMIT();

    for (int c = 0; c < nc2; ++c) {
        int s = c % 3;
        CP_WAIT1();
        __syncthreads();
        const char* st = sm + s * 32768;
#pragma unroll
        for (int kk = 0; kk < 2; ++kk) {
            const uint4* sAh = (const uint4*)(st + kk * 4096);
            const uint4* sAl = (const uint4*)(st + 8192 + kk * 4096);
            const uint4* sBh = (const uint4*)(st + 16384 + kk * 4096);
            const uint4* sBl = (const uint4*)(st + 24576 + kk * 4096);
            uint4 fAh[4], fAl[4], fBh[2], fBl[2];
#pragma unroll
            for (int i = 0; i < 4; i++) {
                fAh[i] = sAh[(wm * 4 + i) * 32 + lane];
                if (ALO) fAl[i] = sAl[(wm * 4 + i) * 32 + lane];
            }
#pragma unroll
            for (int q = 0; q < 2; q++) {
                fBh[q] = sBh[(wn * 2 + q) * 32 + lane];
                if (BLO) fBl[q] = sBl[(wn * 2 + q) * 32 + lane];
            }
#pragma unroll
            for (int i = 0; i < 4; i++) {
#pragma unroll
                for (int j = 0; j < 4; j++) {
                    int q = j >> 1;
                    uint32_t bh0 = (j & 1) ? fBh[q].z : fBh[q].x;
                    uint32_t bh1 = (j & 1) ? fBh[q].w : fBh[q].y;
                    mma16816(acc[i][j], fAh[i], bh0, bh1);
                    if (ALO) mma16816(acc[i][j], fAl[i], bh0, bh1);
                    if (BLO) {
                        uint32_t bl0 = (j & 1) ? fBl[q].z : fBl[q].x;
                        uint32_t bl1 = (j & 1) ? fBl[q].w : fBl[q].y;
                        mma16816(acc[i][j], fAh[i], bl0, bl1);
                    }
                }
            }
        }
        if (c + 2 < nc2) issue((c + 2) % 3, c + 2);
        CP_COMMIT();
    }

    if (RELU) {
#pragma unroll
        for (int i = 0; i < 4; i++)
#pragma unroll
            for (int j = 0; j < 4; j++)
#pragma unroll
                for (int r = 0; r < 4; r++) acc[i][j][r] = fmaxf(acc[i][j][r], 0.f);
    }

    if (MODE == 0) {
        float* Cb = C + (size_t)bz * sCf;
        const int row0 = by * 128 + wm * 64 + (lane >> 2);
        const int colb = bx * 128 + wn * 32 + (lane & 3) * 2;
#pragma unroll
        for (int i = 0; i < 4; i++)
#pragma unroll
            for (int j = 0; j < 4; j++) {
                int r = row0 + i * 16;
                int col = colb + j * 8;
                *reinterpret_cast<float2*>(Cb + (size_t)r * Ncols + col) =
                    make_float2(acc[i][j][0] * outScale, acc[i][j][1] * outScale);
                *reinterpret_cast<float2*>(Cb + (size_t)(r + 8) * Ncols + col) =
                    make_float2(acc[i][j][2] * outScale, acc[i][j][3] * outScale);
            }
    } else if (MODE == 1) {
        // emit A-frags for next GEMM (C-frag layout == A-frag layout)
        const int nkNext = Ncols >> 4;
        const size_t mb = (size_t)bz * mbPerBatch + by;
#pragma unroll
        for (int i = 0; i < 4; i++)
#pragma unroll
            for (int jp = 0; jp < 2; jp++) {
                float h[8], l[8];
#pragma unroll
                for (int r = 0; r < 4; r++) {
                    split2(acc[i][2 * jp][r], h[r], l[r]);
                    split2(acc[i][2 * jp + 1][r], h[4 + r], l[4 + r]);
                }
                int kcg = bx * 8 + wn * 2 + jp;
                size_t di = (mb * nkNext + kcg) * 256 + (wm * 4 + i) * 32 + lane;
                FH[di] = make_uint4(pk(h[0], h[1]), pk(h[2], h[3]),
                                    pk(h[4], h[5]), pk(h[6], h[7]));
                if (FLO)
                    FL[di] = make_uint4(pk(l[0], l[1]), pk(l[2], l[3]),
                                        pk(l[4], l[5]), pk(l[6], l[7]));
            }
    } else {
        // MODE 2: emit B-frags for next GEMM via smem transpose.
        CP_WAIT0();
        __syncthreads();
        float* sf = (float*)sm;  // 128 x 132 fp32
        const int r0 = wm * 64 + (lane >> 2);
        const int c0 = wn * 32 + (lane & 3) * 2;
#pragma unroll
        for (int i = 0; i < 4; i++)
#pragma unroll
            for (int j = 0; j < 4; j++) {
                int rr = r0 + i * 16, cc = c0 + j * 8;
                sf[rr * 132 + cc] = acc[i][j][0];
                sf[rr * 132 + cc + 1] = acc[i][j][1];
                sf[(rr + 8) * 132 + cc] = acc[i][j][2];
                sf[(rr + 8) * 132 + cc + 1] = acc[i][j][3];
            }
        __syncthreads();
        const int batchO = by >> 5;
        const int mbLoc = by & 31;
        const int jj = tid >> 5;
        const int ln = tid & 31;
        const int n0 = 16 * jj + (ln >> 2);
        const int k0b = (ln & 3) * 2;
#pragma unroll
        for (int kb = 0; kb < 8; kb++) {
            int k0 = kb * 16 + k0b;
            float e[8];
            e[0] = sf[k0 * 132 + n0];
            e[1] = sf[(k0 + 1) * 132 + n0];
            e[2] = sf[(k0 + 8) * 132 + n0];
            e[3] = sf[(k0 + 9) * 132 + n0];
            e[4] = sf[k0 * 132 + n0 + 8];
            e[5] = sf[(k0 + 1) * 132 + n0 + 8];
            e[6] = sf[(k0 + 8) * 132 + n0 + 8];
            e[7] = sf[(k0 + 9) * 132 + n0 + 8];
            float h[8], l[8];
#pragma unroll
            for (int r = 0; r < 8; r++) split2(e[r], h[r], l[r]);
            int kc = mbLoc * 8 + kb;
            size_t di = (size_t)batchO * sFu4 + ((size_t)kc * nbX + bx) * 256 + tid;
            FH[di] = make_uint4(pk(h[0], h[1]), pk(h[2], h[3]),
                                pk(h[4], h[5]), pk(h[6], h[7]));
            if (FLO)
                FL[di] = make_uint4(pk(l[0], l[1]), pk(l[2], l[3]),
                                    pk(l[4], l[5]), pk(l[6], l[7]));
        }
    }
}

// ---------------------------------------------------------------------------
template <int MODE, int RELU, int ALO, int BLO, int FLO>
static void launch_gemm(int M, int Ncols, int K,
                        const uint4* Ah, const uint4* Al,
                        const uint4* Bh, const uint4* Bl,
                        float* C, uint4* FH, uint4* FL,
                        int batch, size_t sBu4, size_t sCf,
                        int mbPerBatch, size_t sFu4, float outScale) {
    int nbX = Ncols / 128;
    dim3 g(nbX * batch, M / 128);
    int smem = 3 * 32768;
    cudaFuncSetAttribute(gemm_f16<MODE, RELU, ALO, BLO, FLO>,
                         cudaFuncAttributeMaxDynamicSharedMemorySize, smem);
    gemm_f16<MODE, RELU, ALO, BLO, FLO><<<g, 256, smem>>>(
        Ah, Al, Bh, Bl, C, FH, FL, Ncols, K, nbX, sBu4, sCf, mbPerBatch, sFu4,
        outScale);
}

extern "C" void kernel_launch(void* const* d_in, const int* in_sizes, int n_in,
                              void* d_out, int out_size) {
    const float* x   = (const float*)d_in[0];  // [B, N, 256]
    const float* adj = (const float*)d_in[1];
    const float* S   = (const float*)d_in[2];
    const float* W1  = (const float*)d_in[3];  // [256, 512]
    const float* W2  = (const float*)d_in[4];  // [512, 1024]
    const float* W3  = (const float*)d_in[5];  // [1024, 256]
    float* out = (float*)d_out;                // [B, N, 256]

    uint4 *AwH, *FaH, *FaL, *FbH, *FbL, *WH, *WL;
    cudaGetSymbolAddress((void**)&AwH, g_AwH);
    cudaGetSymbolAddress((void**)&FaH, g_FaH);
    cudaGetSymbolAddress((void**)&FaL, g_FaL);
    cudaGetSymbolAddress((void**)&FbH, g_FbH);
    cudaGetSymbolAddress((void**)&FbL, g_FbL);
    cudaGetSymbolAddress((void**)&WH, g_WH);
    cudaGetSymbolAddress((void**)&WL, g_WL);

    const size_t sX  = (size_t)NN * 256 / 8;   // per-batch u4 strides
    const size_t sH1 = (size_t)NN * 512 / 8;
    const size_t sS3 = (size_t)NN * 256 / 8;

    // One-time preps (coalesced tile kernels)
    prep_A_tile<<<dim3(NN / 64, NN / 128), 256>>>(adj, S, AwH, NN, NN);
    prep_B_tile<<<dim3(2, NN / 32, BB), 256>>>(x, FbH, FbL, NN, 256,
                                               (size_t)NN * 256, sX, XSCALE);
    prep_B_tile<<<dim3(4, 8, 1), 256>>>(W1, WH, WL, 256, 512, 0, 0, 1.0f);
    prep_B_tile<<<dim3(8, 16, 1), 256>>>(W2, WH + 16384, WL + 16384, 512, 1024,
                                         0, 0, 1.0f);
    prep_B_tile<<<dim3(2, 32, 1), 256>>>(W3, WH + 81920, WL + 81920, 1024, 256,
                                         0, 0, 1.0f);

    // G1: t1 = Aw @ x' -> A-frags hi+lo (Fa).  2-product.
    launch_gemm<1, 0, 0, 1, 1>(NN, 256, NN, AwH, nullptr, FbH, FbL, nullptr,
                               FaH, FaL, BB, sX, 0, NN / 128, 0, 1.0f);
    // G2: h1 = relu(t1 @ W1) -> B-frags hi only (Fb).  3-product.
    launch_gemm<2, 1, 1, 1, 0>(BB * NN, 512, 256, FaH, FaL, WH, WL, nullptr,
                               FbH, FbL, 1, 0, 0, 0, sH1, 1.0f);
    // G3: t2 = Aw @ h1 -> A-frags hi+lo (Fa).  1-product.
    launch_gemm<1, 0, 0, 0, 1>(NN, 512, NN, AwH, nullptr, FbH, nullptr,
                               nullptr, FaH, FaL, BB, sH1, 0, NN / 128, 0, 1.0f);
    // G4: h2 = relu(t2 @ W2) -> A-frags hi only (Fb).  3-product.
    launch_gemm<1, 1, 1, 1, 0>(BB * NN, 1024, 512, FaH, FaL, WH + 16384,
                               WL + 16384, nullptr, FbH, FbL, 1, 0, 0, 0, 0,
                               1.0f);
    // G5: s3 = h2 @ W3 -> B-frags hi+lo (Fa).  2-product (A hi only).
    launch_gemm<2, 0, 0, 1, 1>(BB * NN, 256, 1024, FbH, nullptr, WH + 81920,
                               WL + 81920, nullptr, FaH, FaL, 1, 0, 0, 0, sS3,
                               1.0f);
    // G6: out = OSCALE * (Aw @ s3) -> fp32.  2-product.
    launch_gemm<0, 0, 0, 1, 0>(NN, 256, NN, AwH, nullptr, FaH, FaL, out,
                               nullptr, nullptr, BB, sS3, (size_t)NN * 256, 0,
                               0, OSCALE);
}

// round 9
// speedup vs baseline: 10.9890x; 1.2721x over previous
#include <cuda_runtime.h>
#include <cuda_fp16.h>
#include <cstdint>

// GCN — reassociated 3-layer GCN, fp16-split mma.sync, globally scaled.
// x' = x/64; out *= 64 (relu positively homogeneous).
// G1: t1=Aw_h@x_h (1p) -> t1 hi+lo
// G2: h1=relu(t1@W1) (3p) -> h1 hi
// G3: t2=Aw_h@h1_h (1p) -> t2 hi+lo
// G4: h2=relu(t2@W2_h) (2p) -> h2 hi
// G5: s3=h2_h@W3 (2p) -> s3 hi
// G6: out=64*Aw_h@s3_h (1p) -> fp32

#define NN 4096
#define BB 4
#define XSCALE (1.0f / 64.0f)
#define OSCALE 64.0f

// Fragment-tiled storage: A blocks 128m x 16k = 256 uint4 (block = mb*nkc+kc),
// B blocks 16k x 128n = 256 uint4 (block = kc*nnb+nb).
__device__ uint4 g_AwH[(size_t)NN * NN / 8];
__device__ uint4 g_FaH[(size_t)BB * NN * 1024 / 8];  // ping
__device__ uint4 g_FaL[(size_t)BB * NN * 1024 / 8];
__device__ uint4 g_FbH[(size_t)BB * NN * 1024 / 8];  // pong
__device__ uint4 g_FbL[(size_t)BB * NN * 1024 / 8];
__device__ uint4 g_WH[114688];  // W1@0, W2@16384, W3@81920
__device__ uint4 g_WL[114688];

// ---------------------------------------------------------------------------
__device__ __forceinline__ uint32_t smem_u32(const void* p) {
    uint32_t a;
    asm("{ .reg .u64 t; cvta.to.shared.u64 t, %1; cvt.u32.u64 %0, t; }"
        : "=r"(a) : "l"(p));
    return a;
}
__device__ __forceinline__ uint32_t pk(float a, float b) {
    __half2 t = __floats2half2_rn(a, b);
    return *reinterpret_cast<uint32_t*>(&t);
}
__device__ __forceinline__ void split2(float v, float& h, float& l) {
    h = __half2float(__float2half_rn(v));
    l = v - h;
}
__device__ __forceinline__ void cpa16(uint32_t saddr, const void* gaddr) {
    asm volatile("cp.async.cg.shared.global [%0], [%1], 16;"
                 :: "r"(saddr), "l"(gaddr));
}
#define CP_COMMIT() asm volatile("cp.async.commit_group;" ::: "memory")
#define CP_WAIT1()  asm volatile("cp.async.wait_group 1;" ::: "memory")
#define CP_WAIT0()  asm volatile("cp.async.wait_group 0;" ::: "memory")

__device__ __forceinline__ void mma16816(float* c, const uint4& a,
                                         uint32_t b0, uint32_t b1) {
    asm volatile(
        "mma.sync.aligned.m16n8k16.row.col.f32.f16.f16.f32 "
        "{%0,%1,%2,%3},{%4,%5,%6,%7},{%8,%9},{%0,%1,%2,%3};"
        : "+f"(c[0]), "+f"(c[1]), "+f"(c[2]), "+f"(c[3])
        : "r"(a.x), "r"(a.y), "r"(a.z), "r"(a.w), "r"(b0), "r"(b1));
}

// ---------------------------------------------------------------------------
// prep_A_tile: Aw = adj .* S -> A-frag hi only. Coalesced 128x64 tile stage.
// grid: (K/64, M/128), 256 threads.
// ---------------------------------------------------------------------------
__global__ __launch_bounds__(256)
void prep_A_tile(const float* __restrict__ src, const float* __restrict__ mul,
                 uint4* __restrict__ dhi, int M, int K) {
    __shared__ float smt[128][68];
    const int tid = threadIdx.x;
    const int kcb = blockIdx.x;
    const size_t mb = blockIdx.y;
    const int colBase = kcb * 64;
    const size_t rowBase = mb * 128;

    const int c4 = tid & 15;
    const int r0 = tid >> 4;
#pragma unroll
    for (int i = 0; i < 8; i++) {
        int r = r0 + i * 16;
        const float4 v = ((const float4*)(src + (rowBase + r) * K + colBase))[c4];
        const float4 s = ((const float4*)(mul + (rowBase + r) * K + colBase))[c4];
        float4 o = make_float4(v.x * s.x, v.y * s.y, v.z * s.z, v.w * s.w);
        *(float4*)&smt[r][c4 * 4] = o;
    }
    __syncthreads();

    const int lane = tid & 31;
    const int mt = tid >> 5;
    const int rr = mt * 16 + (lane >> 2);
    const int cb = (lane & 3) * 2;
    const int nkc = K >> 4;
#pragma unroll
    for (int kb = 0; kb < 4; kb++) {
        int c0 = kb * 16 + cb;
        uint4 H = make_uint4(
            pk(smt[rr][c0],     smt[rr][c0 + 1]),
            pk(smt[rr + 8][c0], smt[rr + 8][c0 + 1]),
            pk(smt[rr][c0 + 8], smt[rr][c0 + 9]),
            pk(smt[rr + 8][c0 + 8], smt[rr + 8][c0 + 9]));
        dhi[(mb * nkc + (size_t)(kcb * 4 + kb)) * 256 + tid] = H;
    }
}

// ---------------------------------------------------------------------------
// prep_B_tile: src [K,Ncols] f32 * scale -> B-frag hi (+lo). Coalesced
// 32x128 tile stage. grid: (Ncols/128, K/32, batch), 256 threads.
// ---------------------------------------------------------------------------
__global__ __launch_bounds__(256)
void prep_B_tile(const float* __restrict__ src, uint4* __restrict__ dhi,
                 uint4* __restrict__ dlo, int K, int Ncols,
                 size_t sSrc, size_t sDst, float scale) {
    __shared__ float smt[32][132];
    src += (size_t)blockIdx.z * sSrc;
    dhi += (size_t)blockIdx.z * sDst;
    if (dlo) dlo += (size_t)blockIdx.z * sDst;
    const int tid = threadIdx.x;
    const int nb = blockIdx.x;
    const int kcb = blockIdx.y;

    const int c4 = tid & 31;
    const int r0 = tid >> 5;
#pragma unroll
    for (int i = 0; i < 4; i++) {
        int r = r0 + i * 8;
        float4 v = ((const float4*)(src + (size_t)(kcb * 32 + r) * Ncols +
                                    nb * 128))[c4];
        v.x *= scale; v.y *= scale; v.z *= scale; v.w *= scale;
        *(float4*)&smt[r][c4 * 4] = v;
    }
    __syncthreads();

    const int lane = tid & 31;
    const int j = tid >> 5;
    const int n0 = j * 16 + (lane >> 2);
    const int k0b = (lane & 3) * 2;
    const int nnb = Ncols >> 7;
#pragma unroll
    for (int kk = 0; kk < 2; kk++) {
        int k0 = kk * 16 + k0b;
        float e[8];
        e[0] = smt[k0][n0];     e[1] = smt[k0 + 1][n0];
        e[2] = smt[k0 + 8][n0]; e[3] = smt[k0 + 9][n0];
        e[4] = smt[k0][n0 + 8];     e[5] = smt[k0 + 1][n0 + 8];
        e[6] = smt[k0 + 8][n0 + 8]; e[7] = smt[k0 + 9][n0 + 8];
        float h[8], l[8];
#pragma unroll
        for (int r = 0; r < 8; r++) split2(e[r], h[r], l[r]);
        size_t blk = (size_t)(kcb * 2 + kk) * nnb + nb;
        dhi[blk * 256 + tid] = make_uint4(pk(h[0], h[1]), pk(h[2], h[3]),
                                          pk(h[4], h[5]), pk(h[6], h[7]));
        if (dlo)
            dlo[blk * 256 + tid] = make_uint4(pk(l[0], l[1]), pk(l[2], l[3]),
                                              pk(l[4], l[5]), pk(l[6], l[7]));
    }
}

// ---------------------------------------------------------------------------
// GEMM: BM=128, BN=128, BK=32, 3-stage cp.async, 8 warps (2x4), warp 64x32.
// MODE 0: fp32 store (scaled).  MODE 1: emit A-frags.  MODE 2: emit B-frags.
// RELU before emission. ALO/BLO: operand lo present (products = 1+ALO+BLO).
// FLO: emit lo fragments (MODE 1/2).
// grid: x = nbX*batch (bx = x%nbX, bz = x/nbX), y = M/128.
// ---------------------------------------------------------------------------
template <int MODE, int RELU, int ALO, int BLO, int FLO>
__global__ __launch_bounds__(256, 2)
void gemm_f16(const uint4* __restrict__ Ah, const uint4* __restrict__ Al,
              const uint4* __restrict__ Bh, const uint4* __restrict__ Bl,
              float* __restrict__ C, uint4* __restrict__ FH,
              uint4* __restrict__ FL, int Ncols, int K, int nbX,
              size_t sBu4, size_t sCf, int mbPerBatch, size_t sFu4,
              float outScale) {
    extern __shared__ __align__(128) char sm[];
    const int tid = threadIdx.x;
    const int lane = tid & 31;
    const int wid = tid >> 5;
    const int wm = wid >> 2;
    const int wn = wid & 3;
    const int bx = blockIdx.x % nbX;
    const int bz = blockIdx.x / nbX;
    const int by = blockIdx.y;

    Bh += (size_t)bz * sBu4;
    if (BLO) Bl += (size_t)bz * sBu4;

    const int nc2 = K >> 5;
    const int nkc = K >> 4;
    const int nnb = Ncols >> 7;
    const uint32_t sbase = smem_u32(sm);

    float acc[4][4][4];
#pragma unroll
    for (int i = 0; i < 4; i++)
#pragma unroll
        for (int j = 0; j < 4; j++)
#pragma unroll
            for (int r = 0; r < 4; r++) acc[i][j][r] = 0.f;

    auto issue = [&](int s, int c) {
        uint32_t sa = sbase + s * 32768 + tid * 16;
        size_t ab = ((size_t)by * nkc + (size_t)(c << 1)) * 256 + tid;
        size_t bb0 = ((size_t)(c << 1) * nnb + bx) * 256 + tid;
        size_t bb1 = bb0 + (size_t)nnb * 256;
        cpa16(sa,         Ah + ab);
        cpa16(sa + 4096,  Ah + ab + 256);
        if (ALO) {
            cpa16(sa + 8192,  Al + ab);
            cpa16(sa + 12288, Al + ab + 256);
        }
        cpa16(sa + 16384, Bh + bb0);
        cpa16(sa + 20480, Bh + bb1);
        if (BLO) {
            cpa16(sa + 24576, Bl + bb0);
            cpa16(sa + 28672, Bl + bb1);
        }
    };

    issue(0, 0); CP_COMMIT();
    issue(1, 1); CP_COMMIT();

    for (int c = 0; c < nc2; ++c) {
        int s = c % 3;
        CP_WAIT1();
        __syncthreads();
        const char* st = sm + s * 32768;
#pragma unroll
        for (int kk = 0; kk < 2; ++kk) {
            const uint4* sAh = (const uint4*)(st + kk * 4096);
            const uint4* sAl = (const uint4*)(st + 8192 + kk * 4096);
            const uint4* sBh = (const uint4*)(st + 16384 + kk * 4096);
            const uint4* sBl = (const uint4*)(st + 24576 + kk * 4096);
            uint4 fAh[4], fAl[4], fBh[2], fBl[2];
#pragma unroll
            for (int i = 0; i < 4; i++) {
                fAh[i] = sAh[(wm * 4 + i) * 32 + lane];
                if (ALO) fAl[i] = sAl[(wm * 4 + i) * 32 + lane];
            }
#pragma unroll
            for (int q = 0; q < 2; q++) {
                fBh[q] = sBh[(wn * 2 + q) * 32 + lane];
                if (BLO) fBl[q] = sBl[(wn * 2 + q) * 32 + lane];
            }
#pragma unroll
            for (int i = 0; i < 4; i++) {
#pragma unroll
                for (int j = 0; j < 4; j++) {
                    int q = j >> 1;
                    uint32_t bh0 = (j & 1) ? fBh[q].z : fBh[q].x;
                    uint32_t bh1 = (j & 1) ? fBh[q].w : fBh[q].y;
                    mma16816(acc[i][j], fAh[i], bh0, bh1);
                    if (ALO) mma16816(acc[i][j], fAl[i], bh0, bh1);
                    if (BLO) {
                        uint32_t bl0 = (j & 1) ? fBl[q].z : fBl[q].x;
                        uint32_t bl1 = (j & 1) ? fBl[q].w : fBl[q].y;
                        mma16816(acc[i][j], fAh[i], bl0, bl1);
                    }
                }
            }
        }
        if (c + 2 < nc2) issue((c + 2) % 3, c + 2);
        CP_COMMIT();
    }

    if (RELU) {
#pragma unroll
        for (int i = 0; i < 4; i++)
#pragma unroll
            for (int j = 0; j < 4; j++)
#pragma unroll
                for (int r = 0; r < 4; r++) acc[i][j][r] = fmaxf(acc[i][j][r], 0.f);
    }

    if (MODE == 0) {
        float* Cb = C + (size_t)bz * sCf;
        const int row0 = by * 128 + wm * 64 + (lane >> 2);
        const int colb = bx * 128 + wn * 32 + (lane & 3) * 2;
#pragma unroll
        for (int i = 0; i < 4; i++)
#pragma unroll
            for (int j = 0; j < 4; j++) {
                int r = row0 + i * 16;
                int col = colb + j * 8;
                *reinterpret_cast<float2*>(Cb + (size_t)r * Ncols + col) =
                    make_float2(acc[i][j][0] * outScale, acc[i][j][1] * outScale);
                *reinterpret_cast<float2*>(Cb + (size_t)(r + 8) * Ncols + col) =
                    make_float2(acc[i][j][2] * outScale, acc[i][j][3] * outScale);
            }
    } else if (MODE == 1) {
        // emit A-frags for next GEMM (C-frag layout == A-frag layout)
        const int nkNext = Ncols >> 4;
        const size_t mb = (size_t)bz * mbPerBatch + by;
#pragma unroll
        for (int i = 0; i < 4; i++)
#pragma unroll
            for (int jp = 0; jp < 2; jp++) {
                float h[8], l[8];
#pragma unroll
                for (int r = 0; r < 4; r++) {
                    split2(acc[i][2 * jp][r], h[r], l[r]);
                    split2(acc[i][2 * jp + 1][r], h[4 + r], l[4 + r]);
                }
                int kcg = bx * 8 + wn * 2 + jp;
                size_t di = (mb * nkNext + kcg) * 256 + (wm * 4 + i) * 32 + lane;
                FH[di] = make_uint4(pk(h[0], h[1]), pk(h[2], h[3]),
                                    pk(h[4], h[5]), pk(h[6], h[7]));
                if (FLO)
                    FL[di] = make_uint4(pk(l[0], l[1]), pk(l[2], l[3]),
                                        pk(l[4], l[5]), pk(l[6], l[7]));
            }
    } else {
        // MODE 2: emit B-frags for next GEMM via smem transpose.
        CP_WAIT0();
        __syncthreads();
        float* sf = (float*)sm;  // 128 x 132 fp32
        const int r0 = wm * 64 + (lane >> 2);
        const int c0 = wn * 32 + (lane & 3) * 2;
#pragma unroll
        for (int i = 0; i < 4; i++)
#pragma unroll
            for (int j = 0; j < 4; j++) {
                int rr = r0 + i * 16, cc = c0 + j * 8;
                sf[rr * 132 + cc] = acc[i][j][0];
                sf[rr * 132 + cc + 1] = acc[i][j][1];
                sf[(rr + 8) * 132 + cc] = acc[i][j][2];
                sf[(rr + 8) * 132 + cc + 1] = acc[i][j][3];
            }
        __syncthreads();
        const int batchO = by >> 5;
        const int mbLoc = by & 31;
        const int jj = tid >> 5;
        const int ln = tid & 31;
        const int n0 = 16 * jj + (ln >> 2);
        const int k0b = (ln & 3) * 2;
#pragma unroll
        for (int kb = 0; kb < 8; kb++) {
            int k0 = kb * 16 + k0b;
            float e[8];
            e[0] = sf[k0 * 132 + n0];
            e[1] = sf[(k0 + 1) * 132 + n0];
            e[2] = sf[(k0 + 8) * 132 + n0];
            e[3] = sf[(k0 + 9) * 132 + n0];
            e[4] = sf[k0 * 132 + n0 + 8];
            e[5] = sf[(k0 + 1) * 132 + n0 + 8];
            e[6] = sf[(k0 + 8) * 132 + n0 + 8];
            e[7] = sf[(k0 + 9) * 132 + n0 + 8];
            float h[8], l[8];
#pragma unroll
            for (int r = 0; r < 8; r++) split2(e[r], h[r], l[r]);
            int kc = mbLoc * 8 + kb;
            size_t di = (size_t)batchO * sFu4 + ((size_t)kc * nbX + bx) * 256 + tid;
            FH[di] = make_uint4(pk(h[0], h[1]), pk(h[2], h[3]),
                                pk(h[4], h[5]), pk(h[6], h[7]));
            if (FLO)
                FL[di] = make_uint4(pk(l[0], l[1]), pk(l[2], l[3]),
                                    pk(l[4], l[5]), pk(l[6], l[7]));
        }
    }
}

// ---------------------------------------------------------------------------
template <int MODE, int RELU, int ALO, int BLO, int FLO>
static void launch_gemm(int M, int Ncols, int K,
                        const uint4* Ah, const uint4* Al,
                        const uint4* Bh, const uint4* Bl,
                        float* C, uint4* FH, uint4* FL,
                        int batch, size_t sBu4, size_t sCf,
                        int mbPerBatch, size_t sFu4, float outScale) {
    int nbX = Ncols / 128;
    dim3 g(nbX * batch, M / 128);
    int smem = 3 * 32768;
    cudaFuncSetAttribute(gemm_f16<MODE, RELU, ALO, BLO, FLO>,
                         cudaFuncAttributeMaxDynamicSharedMemorySize, smem);
    gemm_f16<MODE, RELU, ALO, BLO, FLO><<<g, 256, smem>>>(
        Ah, Al, Bh, Bl, C, FH, FL, Ncols, K, nbX, sBu4, sCf, mbPerBatch, sFu4,
        outScale);
}

extern "C" void kernel_launch(void* const* d_in, const int* in_sizes, int n_in,
                              void* d_out, int out_size) {
    const float* x   = (const float*)d_in[0];  // [B, N, 256]
    const float* adj = (const float*)d_in[1];
    const float* S   = (const float*)d_in[2];
    const float* W1  = (const float*)d_in[3];  // [256, 512]
    const float* W2  = (const float*)d_in[4];  // [512, 1024]
    const float* W3  = (const float*)d_in[5];  // [1024, 256]
    float* out = (float*)d_out;                // [B, N, 256]

    uint4 *AwH, *FaH, *FaL, *FbH, *FbL, *WH, *WL;
    cudaGetSymbolAddress((void**)&AwH, g_AwH);
    cudaGetSymbolAddress((void**)&FaH, g_FaH);
    cudaGetSymbolAddress((void**)&FaL, g_FaL);
    cudaGetSymbolAddress((void**)&FbH, g_FbH);
    cudaGetSymbolAddress((void**)&FbL, g_FbL);
    cudaGetSymbolAddress((void**)&WH, g_WH);
    cudaGetSymbolAddress((void**)&WL, g_WL);

    const size_t sX  = (size_t)NN * 256 / 8;   // per-batch u4 strides
    const size_t sH1 = (size_t)NN * 512 / 8;
    const size_t sS3 = (size_t)NN * 256 / 8;

    // One-time preps (coalesced tile kernels)
    prep_A_tile<<<dim3(NN / 64, NN / 128), 256>>>(adj, S, AwH, NN, NN);
    // x: hi only (G1 is 1-product)
    prep_B_tile<<<dim3(2, NN / 32, BB), 256>>>(x, FbH, nullptr, NN, 256,
                                               (size_t)NN * 256, sX, XSCALE);
    prep_B_tile<<<dim3(4, 8, 1), 256>>>(W1, WH, WL, 256, 512, 0, 0, 1.0f);
    // W2: hi only (G4 is 2-product, A-lo kept)
    prep_B_tile<<<dim3(8, 16, 1), 256>>>(W2, WH + 16384, nullptr, 512, 1024,
                                         0, 0, 1.0f);
    prep_B_tile<<<dim3(2, 32, 1), 256>>>(W3, WH + 81920, WL + 81920, 1024, 256,
                                         0, 0, 1.0f);

    // G1: t1 = Aw_h @ x_h -> A-frags hi+lo (Fa).  1-product.
    launch_gemm<1, 0, 0, 0, 1>(NN, 256, NN, AwH, nullptr, FbH, nullptr,
                               nullptr, FaH, FaL, BB, sX, 0, NN / 128, 0, 1.0f);
    // G2: h1 = relu(t1 @ W1) -> B-frags hi only (Fb).  3-product.
    launch_gemm<2, 1, 1, 1, 0>(BB * NN, 512, 256, FaH, FaL, WH, WL, nullptr,
                               FbH, FbL, 1, 0, 0, 0, sH1, 1.0f);
    // G3: t2 = Aw_h @ h1_h -> A-frags hi+lo (Fa).  1-product.
    launch_gemm<1, 0, 0, 0, 1>(NN, 512, NN, AwH, nullptr, FbH, nullptr,
                               nullptr, FaH, FaL, BB, sH1, 0, NN / 128, 0, 1.0f);
    // G4: h2 = relu(t2 @ W2_h) -> A-frags hi only (Fb).  2-product (A-lo).
    launch_gemm<1, 1, 1, 0, 0>(BB * NN, 1024, 512, FaH, FaL, WH + 16384,
                               nullptr, nullptr, FbH, FbL, 1, 0, 0, 0, 0, 1.0f);
    // G5: s3 = h2_h @ W3 -> B-frags hi only (Fa).  2-product (B-lo).
    launch_gemm<2, 0, 0, 1, 0>(BB * NN, 256, 1024, FbH, nullptr, WH + 81920,
                               WL + 81920, nullptr, FaH, FaL, 1, 0, 0, 0, sS3,
                               1.0f);
    // G6: out = OSCALE * (Aw_h @ s3_h) -> fp32.  1-product.
    launch_gemm<0, 0, 0, 0, 0>(NN, 256, NN, AwH, nullptr, FaH, nullptr, out,
                               nullptr, nullptr, BB, sS3, (size_t)NN * 256, 0,
                               0, OSCALE);
}

// round 10
// speedup vs baseline: 11.8292x; 1.0765x over previous
#include <cuda_runtime.h>
#include <cuda_fp16.h>
#include <cstdint>

// GCN — reassociated 3-layer GCN, fp16-split mma.sync, globally scaled.
// x' = x/64; out *= 64 (relu positively homogeneous).
// G1: t1=Aw_h@x_h (1p) -> t1 hi
// G2: h1=relu(t1_h@(W1_h+W1_l)) (2p) -> h1 hi
// G3: t2=Aw_h@h1_h (1p) -> t2 hi
// G4: h2=relu(t2_h@W2_h) (1p) -> h2 hi
// G5: s3=h2_h@(W3_h+W3_l) (2p) -> s3 hi
// G6: out=64*Aw_h@s3_h (1p) -> fp32

#define NN 4096
#define BB 4
#define XSCALE (1.0f / 64.0f)
#define OSCALE 64.0f

// Fragment-tiled storage: A blocks 128m x 16k = 256 uint4 (block = mb*nkc+kc),
// B blocks 16k x 128n = 256 uint4 (block = kc*nnb+nb).
__device__ uint4 g_AwH[(size_t)NN * NN / 8];
__device__ uint4 g_FaH[(size_t)BB * NN * 1024 / 8];  // ping
__device__ uint4 g_FbH[(size_t)BB * NN * 1024 / 8];  // pong
__device__ uint4 g_WH[114688];  // W1@0, W2@16384, W3@81920
__device__ uint4 g_WL[114688];

// ---------------------------------------------------------------------------
__device__ __forceinline__ uint32_t smem_u32(const void* p) {
    uint32_t a;
    asm("{ .reg .u64 t; cvta.to.shared.u64 t, %1; cvt.u32.u64 %0, t; }"
        : "=r"(a) : "l"(p));
    return a;
}
__device__ __forceinline__ uint32_t pk(float a, float b) {
    __half2 t = __floats2half2_rn(a, b);
    return *reinterpret_cast<uint32_t*>(&t);
}
__device__ __forceinline__ void split2(float v, float& h, float& l) {
    h = __half2float(__float2half_rn(v));
    l = v - h;
}
__device__ __forceinline__ void cpa16(uint32_t saddr, const void* gaddr) {
    asm volatile("cp.async.cg.shared.global [%0], [%1], 16;"
                 :: "r"(saddr), "l"(gaddr));
}
#define CP_COMMIT() asm volatile("cp.async.commit_group;" ::: "memory")
#define CP_WAIT1()  asm volatile("cp.async.wait_group 1;" ::: "memory")
#define CP_WAIT0()  asm volatile("cp.async.wait_group 0;" ::: "memory")

__device__ __forceinline__ void mma16816(float* c, const uint4& a,
                                         uint32_t b0, uint32_t b1) {
    asm volatile(
        "mma.sync.aligned.m16n8k16.row.col.f32.f16.f16.f32 "
        "{%0,%1,%2,%3},{%4,%5,%6,%7},{%8,%9},{%0,%1,%2,%3};"
        : "+f"(c[0]), "+f"(c[1]), "+f"(c[2]), "+f"(c[3])
        : "r"(a.x), "r"(a.y), "r"(a.z), "r"(a.w), "r"(b0), "r"(b1));
}

// ---------------------------------------------------------------------------
// prep_A_tile: Aw = adj .* S -> A-frag hi only. Coalesced 128x64 tile stage.
// grid: (K/64, M/128), 256 threads.
// ---------------------------------------------------------------------------
__global__ __launch_bounds__(256)
void prep_A_tile(const float* __restrict__ src, const float* __restrict__ mul,
                 uint4* __restrict__ dhi, int M, int K) {
    __shared__ float smt[128][68];
    const int tid = threadIdx.x;
    const int kcb = blockIdx.x;
    const size_t mb = blockIdx.y;
    const int colBase = kcb * 64;
    const size_t rowBase = mb * 128;

    const int c4 = tid & 15;
    const int r0 = tid >> 4;
#pragma unroll
    for (int i = 0; i < 8; i++) {
        int r = r0 + i * 16;
        const float4 v = ((const float4*)(src + (rowBase + r) * K + colBase))[c4];
        const float4 s = ((const float4*)(mul + (rowBase + r) * K + colBase))[c4];
        float4 o = make_float4(v.x * s.x, v.y * s.y, v.z * s.z, v.w * s.w);
        *(float4*)&smt[r][c4 * 4] = o;
    }
    __syncthreads();

    const int lane = tid & 31;
    const int mt = tid >> 5;
    const int rr = mt * 16 + (lane >> 2);
    const int cb = (lane & 3) * 2;
    const int nkc = K >> 4;
#pragma unroll
    for (int kb = 0; kb < 4; kb++) {
        int c0 = kb * 16 + cb;
        uint4 H = make_uint4(
            pk(smt[rr][c0],     smt[rr][c0 + 1]),
            pk(smt[rr + 8][c0], smt[rr + 8][c0 + 1]),
            pk(smt[rr][c0 + 8], smt[rr][c0 + 9]),
            pk(smt[rr + 8][c0 + 8], smt[rr + 8][c0 + 9]));
        dhi[(mb * nkc + (size_t)(kcb * 4 + kb)) * 256 + tid] = H;
    }
}

// ---------------------------------------------------------------------------
// prep_B_tile: src [K,Ncols] f32 * scale -> B-frag hi (+lo). Coalesced
// 32x128 tile stage. grid: (Ncols/128, K/32, batch), 256 threads.
// ---------------------------------------------------------------------------
__global__ __launch_bounds__(256)
void prep_B_tile(const float* __restrict__ src, uint4* __restrict__ dhi,
                 uint4* __restrict__ dlo, int K, int Ncols,
                 size_t sSrc, size_t sDst, float scale) {
    __shared__ float smt[32][132];
    src += (size_t)blockIdx.z * sSrc;
    dhi += (size_t)blockIdx.z * sDst;
    if (dlo) dlo += (size_t)blockIdx.z * sDst;
    const int tid = threadIdx.x;
    const int nb = blockIdx.x;
    const int kcb = blockIdx.y;

    const int c4 = tid & 31;
    const int r0 = tid >> 5;
#pragma unroll
    for (int i = 0; i < 4; i++) {
        int r = r0 + i * 8;
        float4 v = ((const float4*)(src + (size_t)(kcb * 32 + r) * Ncols +
                                    nb * 128))[c4];
        v.x *= scale; v.y *= scale; v.z *= scale; v.w *= scale;
        *(float4*)&smt[r][c4 * 4] = v;
    }
    __syncthreads();

    const int lane = tid & 31;
    const int j = tid >> 5;
    const int n0 = j * 16 + (lane >> 2);
    const int k0b = (lane & 3) * 2;
    const int nnb = Ncols >> 7;
#pragma unroll
    for (int kk = 0; kk < 2; kk++) {
        int k0 = kk * 16 + k0b;
        float e[8];
        e[0] = smt[k0][n0];     e[1] = smt[k0 + 1][n0];
        e[2] = smt[k0 + 8][n0]; e[3] = smt[k0 + 9][n0];
        e[4] = smt[k0][n0 + 8];     e[5] = smt[k0 + 1][n0 + 8];
        e[6] = smt[k0 + 8][n0 + 8]; e[7] = smt[k0 + 9][n0 + 8];
        float h[8], l[8];
#pragma unroll
        for (int r = 0; r < 8; r++) split2(e[r], h[r], l[r]);
        size_t blk = (size_t)(kcb * 2 + kk) * nnb + nb;
        dhi[blk * 256 + tid] = make_uint4(pk(h[0], h[1]), pk(h[2], h[3]),
                                          pk(h[4], h[5]), pk(h[6], h[7]));
        if (dlo)
            dlo[blk * 256 + tid] = make_uint4(pk(l[0], l[1]), pk(l[2], l[3]),
                                              pk(l[4], l[5]), pk(l[6], l[7]));
    }
}

// ---------------------------------------------------------------------------
// GEMM: BM=128, BN=128, BK=32, 3-stage cp.async, 8 warps (2x4), warp 64x32.
// MODE 0: fp32 store (scaled).  MODE 1: emit A-frags (hi only).
// MODE 2: emit B-frags (hi only, smem transpose).  RELU before emission.
// ALO/BLO: operand lo present (products = 1+ALO+BLO).
// grid: x = nbX*batch (bx = x%nbX, bz = x/nbX), y = M/128.
// ---------------------------------------------------------------------------
template <int MODE, int RELU, int ALO, int BLO>
__global__ __launch_bounds__(256, 2)
void gemm_f16(const uint4* __restrict__ Ah, const uint4* __restrict__ Al,
              const uint4* __restrict__ Bh, const uint4* __restrict__ Bl,
              float* __restrict__ C, uint4* __restrict__ FH,
              int Ncols, int K, int nbX,
              size_t sBu4, size_t sCf, int mbPerBatch, size_t sFu4,
              float outScale) {
    extern __shared__ __align__(128) char sm[];
    const int tid = threadIdx.x;
    const int lane = tid & 31;
    const int wid = tid >> 5;
    const int wm = wid >> 2;
    const int wn = wid & 3;
    const int bx = blockIdx.x % nbX;
    const int bz = blockIdx.x / nbX;
    const int by = blockIdx.y;

    Bh += (size_t)bz * sBu4;
    if (BLO) Bl += (size_t)bz * sBu4;

    const int nc2 = K >> 5;
    const int nkc = K >> 4;
    const int nnb = Ncols >> 7;
    const uint32_t sbase = smem_u32(sm);

    float acc[4][4][4];
#pragma unroll
    for (int i = 0; i < 4; i++)
#pragma unroll
        for (int j = 0; j < 4; j++)
#pragma unroll
            for (int r = 0; r < 4; r++) acc[i][j][r] = 0.f;

    auto issue = [&](int s, int c) {
        uint32_t sa = sbase + s * 32768 + tid * 16;
        size_t ab = ((size_t)by * nkc + (size_t)(c << 1)) * 256 + tid;
        size_t bb0 = ((size_t)(c << 1) * nnb + bx) * 256 + tid;
        size_t bb1 = bb0 + (size_t)nnb * 256;
        cpa16(sa,         Ah + ab);
        cpa16(sa + 4096,  Ah + ab + 256);
        if (ALO) {
            cpa16(sa + 8192,  Al + ab);
            cpa16(sa + 12288, Al + ab + 256);
        }
        cpa16(sa + 16384, Bh + bb0);
        cpa16(sa + 20480, Bh + bb1);
        if (BLO) {
            cpa16(sa + 24576, Bl + bb0);
            cpa16(sa + 28672, Bl + bb1);
        }
    };

    issue(0, 0); CP_COMMIT();
    issue(1, 1); CP_COMMIT();

    for (int c = 0; c < nc2; ++c) {
        int s = c % 3;
        CP_WAIT1();
        __syncthreads();
        const char* st = sm + s * 32768;
#pragma unroll
        for (int kk = 0; kk < 2; ++kk) {
            const uint4* sAh = (const uint4*)(st + kk * 4096);
            const uint4* sAl = (const uint4*)(st + 8192 + kk * 4096);
            const uint4* sBh = (const uint4*)(st + 16384 + kk * 4096);
            const uint4* sBl = (const uint4*)(st + 24576 + kk * 4096);
            uint4 fAh[4], fAl[4], fBh[2], fBl[2];
#pragma unroll
            for (int i = 0; i < 4; i++) {
                fAh[i] = sAh[(wm * 4 + i) * 32 + lane];
                if (ALO) fAl[i] = sAl[(wm * 4 + i) * 32 + lane];
            }
#pragma unroll
            for (int q = 0; q < 2; q++) {
                fBh[q] = sBh[(wn * 2 + q) * 32 + lane];
                if (BLO) fBl[q] = sBl[(wn * 2 + q) * 32 + lane];
            }
#pragma unroll
            for (int i = 0; i < 4; i++) {
#pragma unroll
                for (int j = 0; j < 4; j++) {
                    int q = j >> 1;
                    uint32_t bh0 = (j & 1) ? fBh[q].z : fBh[q].x;
                    uint32_t bh1 = (j & 1) ? fBh[q].w : fBh[q].y;
                    mma16816(acc[i][j], fAh[i], bh0, bh1);
                    if (ALO) mma16816(acc[i][j], fAl[i], bh0, bh1);
                    if (BLO) {
                        uint32_t bl0 = (j & 1) ? fBl[q].z : fBl[q].x;
                        uint32_t bl1 = (j & 1) ? fBl[q].w : fBl[q].y;
                        mma16816(acc[i][j], fAh[i], bl0, bl1);
                    }
                }
            }
        }
        if (c + 2 < nc2) issue((c + 2) % 3, c + 2);
        CP_COMMIT();
    }

    if (RELU) {
#pragma unroll
        for (int i = 0; i < 4; i++)
#pragma unroll
            for (int j = 0; j < 4; j++)
#pragma unroll
                for (int r = 0; r < 4; r++) acc[i][j][r] = fmaxf(acc[i][j][r], 0.f);
    }

    if (MODE == 0) {
        float* Cb = C + (size_t)bz * sCf;
        const int row0 = by * 128 + wm * 64 + (lane >> 2);
        const int colb = bx * 128 + wn * 32 + (lane & 3) * 2;
#pragma unroll
        for (int i = 0; i < 4; i++)
#pragma unroll
            for (int j = 0; j < 4; j++) {
                int r = row0 + i * 16;
                int col = colb + j * 8;
                *reinterpret_cast<float2*>(Cb + (size_t)r * Ncols + col) =
                    make_float2(acc[i][j][0] * outScale, acc[i][j][1] * outScale);
                *reinterpret_cast<float2*>(Cb + (size_t)(r + 8) * Ncols + col) =
                    make_float2(acc[i][j][2] * outScale, acc[i][j][3] * outScale);
            }
    } else if (MODE == 1) {
        // emit A-frags (hi) for next GEMM (C-frag layout == A-frag layout)
        const int nkNext = Ncols >> 4;
        const size_t mb = (size_t)bz * mbPerBatch + by;
#pragma unroll
        for (int i = 0; i < 4; i++)
#pragma unroll
            for (int jp = 0; jp < 2; jp++) {
                float* a0 = acc[i][2 * jp];
                float* a1 = acc[i][2 * jp + 1];
                int kcg = bx * 8 + wn * 2 + jp;
                size_t di = (mb * nkNext + kcg) * 256 + (wm * 4 + i) * 32 + lane;
                FH[di] = make_uint4(pk(a0[0], a0[1]), pk(a0[2], a0[3]),
                                    pk(a1[0], a1[1]), pk(a1[2], a1[3]));
            }
    } else {
        // MODE 2: emit B-frags (hi) for next GEMM via smem transpose.
        CP_WAIT0();
        __syncthreads();
        float* sf = (float*)sm;  // 128 x 132 fp32
        const int r0 = wm * 64 + (lane >> 2);
        const int c0 = wn * 32 + (lane & 3) * 2;
#pragma unroll
        for (int i = 0; i < 4; i++)
#pragma unroll
            for (int j = 0; j < 4; j++) {
                int rr = r0 + i * 16, cc = c0 + j * 8;
                sf[rr * 132 + cc] = acc[i][j][0];
                sf[rr * 132 + cc + 1] = acc[i][j][1];
                sf[(rr + 8) * 132 + cc] = acc[i][j][2];
                sf[(rr + 8) * 132 + cc + 1] = acc[i][j][3];
            }
        __syncthreads();
        const int batchO = by >> 5;
        const int mbLoc = by & 31;
        const int jj = tid >> 5;
        const int ln = tid & 31;
        const int n0 = 16 * jj + (ln >> 2);
        const int k0b = (ln & 3) * 2;
#pragma unroll
        for (int kb = 0; kb < 8; kb++) {
            int k0 = kb * 16 + k0b;
            float e[8];
            e[0] = sf[k0 * 132 + n0];
            e[1] = sf[(k0 + 1) * 132 + n0];
            e[2] = sf[(k0 + 8) * 132 + n0];
            e[3] = sf[(k0 + 9) * 132 + n0];
            e[4] = sf[k0 * 132 + n0 + 8];
            e[5] = sf[(k0 + 1) * 132 + n0 + 8];
            e[6] = sf[(k0 + 8) * 132 + n0 + 8];
            e[7] = sf[(k0 + 9) * 132 + n0 + 8];
            int kc = mbLoc * 8 + kb;
            size_t di = (size_t)batchO * sFu4 + ((size_t)kc * nbX + bx) * 256 + tid;
            FH[di] = make_uint4(pk(e[0], e[1]), pk(e[2], e[3]),
                                pk(e[4], e[5]), pk(e[6], e[7]));
        }
    }
}

// ---------------------------------------------------------------------------
template <int MODE, int RELU, int ALO, int BLO>
static void launch_gemm(int M, int Ncols, int K,
                        const uint4* Ah, const uint4* Al,
                        const uint4* Bh, const uint4* Bl,
                        float* C, uint4* FH,
                        int batch, size_t sBu4, size_t sCf,
                        int mbPerBatch, size_t sFu4, float outScale) {
    int nbX = Ncols / 128;
    dim3 g(nbX * batch, M / 128);
    int smem = 3 * 32768;
    cudaFuncSetAttribute(gemm_f16<MODE, RELU, ALO, BLO>,
                         cudaFuncAttributeMaxDynamicSharedMemorySize, smem);
    gemm_f16<MODE, RELU, ALO, BLO><<<g, 256, smem>>>(
        Ah, Al, Bh, Bl, C, FH, Ncols, K, nbX, sBu4, sCf, mbPerBatch, sFu4,
        outScale);
}

extern "C" void kernel_launch(void* const* d_in, const int* in_sizes, int n_in,
                              void* d_out, int out_size) {
    const float* x   = (const float*)d_in[0];  // [B, N, 256]
    const float* adj = (const float*)d_in[1];
    const float* S   = (const float*)d_in[2];
    const float* W1  = (const float*)d_in[3];  // [256, 512]
    const float* W2  = (const float*)d_in[4];  // [512, 1024]
    const float* W3  = (const float*)d_in[5];  // [1024, 256]
    float* out = (float*)d_out;                // [B, N, 256]

    uint4 *AwH, *FaH, *FbH, *WH, *WL;
    cudaGetSymbolAddress((void**)&AwH, g_AwH);
    cudaGetSymbolAddress((void**)&FaH, g_FaH);
    cudaGetSymbolAddress((void**)&FbH, g_FbH);
    cudaGetSymbolAddress((void**)&WH, g_WH);
    cudaGetSymbolAddress((void**)&WL, g_WL);

    const size_t sX  = (size_t)NN * 256 / 8;   // per-batch u4 strides
    const size_t sH1 = (size_t)NN * 512 / 8;
    const size_t sS3 = (size_t)NN * 256 / 8;

    // One-time preps (coalesced tile kernels)
    prep_A_tile<<<dim3(NN / 64, NN / 128), 256>>>(adj, S, AwH, NN, NN);
    // x: hi only (G1 is 1-product)
    prep_B_tile<<<dim3(2, NN / 32, BB), 256>>>(x, FbH, nullptr, NN, 256,
                                               (size_t)NN * 256, sX, XSCALE);
    prep_B_tile<<<dim3(4, 8, 1), 256>>>(W1, WH, WL, 256, 512, 0, 0, 1.0f);
    // W2: hi only (G4 is 1-product)
    prep_B_tile<<<dim3(8, 16, 1), 256>>>(W2, WH + 16384, nullptr, 512, 1024,
                                         0, 0, 1.0f);
    prep_B_tile<<<dim3(2, 32, 1), 256>>>(W3, WH + 81920, WL + 81920, 1024, 256,
                                         0, 0, 1.0f);

    // G1: t1 = Aw_h @ x_h -> A-frags hi (Fa).  1-product.
    launch_gemm<1, 0, 0, 0>(NN, 256, NN, AwH, nullptr, FbH, nullptr,
                            nullptr, FaH, BB, sX, 0, NN / 128, 0, 1.0f);
    // G2: h1 = relu(t1_h @ (W1_h+W1_l)) -> B-frags hi (Fb).  2-product.
    launch_gemm<2, 1, 0, 1>(BB * NN, 512, 256, FaH, nullptr, WH, WL, nullptr,
                            FbH, 1, 0, 0, 0, sH1, 1.0f);
    // G3: t2 = Aw_h @ h1_h -> A-frags hi (Fa).  1-product.
    launch_gemm<1, 0, 0, 0>(NN, 512, NN, AwH, nullptr, FbH, nullptr,
                            nullptr, FaH, BB, sH1, 0, NN / 128, 0, 1.0f);
    // G4: h2 = relu(t2_h @ W2_h) -> A-frags hi (Fb).  1-product.
    launch_gemm<1, 1, 0, 0>(BB * NN, 1024, 512, FaH, nullptr, WH + 16384,
                            nullptr, nullptr, FbH, 1, 0, 0, 0, 0, 1.0f);
    // G5: s3 = h2_h @ (W3_h+W3_l) -> B-frags hi (Fa).  2-product.
    launch_gemm<2, 0, 0, 1>(BB * NN, 256, 1024, FbH, nullptr, WH + 81920,
                            WL + 81920, nullptr, FaH, 1, 0, 0, 0, sS3, 1.0f);
    // G6: out = OSCALE * (Aw_h @ s3_h) -> fp32.  1-product.
    launch_gemm<0, 0, 0, 0>(NN, 256, NN, AwH, nullptr, FaH, nullptr, out,
                            nullptr, BB, sS3, (size_t)NN * 256, 0, 0, OSCALE);
}